// round 12
// baseline (speedup 1.0000x reference)
#include <cuda_runtime.h>
#include <cuda_bf16.h>
#include <math.h>
#include <stdint.h>

#define TT 8
#define NCC 512
#define NTT 512
#define DD 256
#define HH 8
#define LBL 3
#define NBF 1419
#define EPS_ 1e-4f
#define DN 0.25f
#define DN2 0.0625f
#define RATIO 0.026549364f

typedef long long ll;

// ---------------- fp32 scratch ----------------
__device__ float g_xc[TT*NCC*(DD+LBL)];
__device__ float g_h1[TT*NCC*DD];
__device__ float g_h2[TT*NCC*DD];
__device__ float g_cf[TT*NCC*DD];
__device__ float g_k[TT*HH*NCC*DD];
__device__ float g_v[TT*HH*NCC*DD];
__device__ float g_q[TT*HH*NTT*DD];
__device__ float g_qp[(ll)TT*HH*NTT*NBF];
__device__ float g_kp[(ll)TT*HH*NCC*NBF];
__device__ float g_ksum[TT*HH*NBF];
__device__ float g_kmxp[TT*HH*8];
__device__ float g_dinv[TT*HH*NTT];
__device__ float g_ctx[(ll)TT*HH*NBF*DD];
__device__ float g_om[TT*NTT*HH*DD];
__device__ float g_rep[TT*NTT*DD];
__device__ float g_scA[131072];
__device__ float g_scB[131072];

// ---------------- int8 operand pools (tiles: 128 rows x 128 int8 = 16KB) ----------------
#define PA_SZ 50331648LL   // step5 A: 64*12*4*16384
#define PB_SZ 25165824LL   // step6 B: 64*2*12*16384
__device__ __align__(16) int8_t pAq1[PA_SZ], pAq2[PA_SZ];
__device__ __align__(16) int8_t pBq1[PB_SZ], pBq2[PB_SZ];

// ---------------- PTX helpers ----------------
__device__ __forceinline__ uint32_t smem_u32(const void* p) {
    uint32_t a;
    asm("{ .reg .u64 t; cvta.to.shared.u64 t, %1; cvt.u32.u64 %0, t; }" : "=r"(a) : "l"(p));
    return a;
}
__device__ __forceinline__ void cpa16(uint32_t s, const void* g) {
    asm volatile("cp.async.cg.shared.global [%0], [%1], 16;" :: "r"(s), "l"(g));
}
__device__ __forceinline__ void ldsm4(uint32_t* r, uint32_t addr) {
    asm volatile("ldmatrix.sync.aligned.m8n8.x4.shared.b16 {%0,%1,%2,%3}, [%4];"
        : "=r"(r[0]), "=r"(r[1]), "=r"(r[2]), "=r"(r[3]) : "r"(addr));
}
__device__ __forceinline__ void imma(int* c, const uint32_t* a, uint32_t b0, uint32_t b1) {
    asm volatile("mma.sync.aligned.m16n8k32.row.col.s32.s8.s8.s32 "
        "{%0,%1,%2,%3}, {%4,%5,%6,%7}, {%8,%9}, {%0,%1,%2,%3};"
        : "+r"(c[0]), "+r"(c[1]), "+r"(c[2]), "+r"(c[3])
        : "r"(a[0]), "r"(a[1]), "r"(a[2]), "r"(a[3]), "r"(b0), "r"(b1));
}
__device__ __forceinline__ uint32_t swz(uint32_t off) {
    return off ^ ((off >> 3) & 0x70);
}

// ---------------- reductions ----------------
__device__ __forceinline__ float blk_sum(float v) {
    __shared__ float sh[32];
    int lane = threadIdx.x & 31, w = threadIdx.x >> 5;
#pragma unroll
    for (int o = 16; o; o >>= 1) v += __shfl_xor_sync(0xffffffffu, v, o);
    __syncthreads();
    if (lane == 0) sh[w] = v;
    __syncthreads();
    float r = (threadIdx.x < (blockDim.x >> 5)) ? sh[threadIdx.x] : 0.f;
    if (w == 0) {
#pragma unroll
        for (int o = 16; o; o >>= 1) r += __shfl_xor_sync(0xffffffffu, r, o);
        if (lane == 0) sh[0] = r;
    }
    __syncthreads();
    return sh[0];
}
__device__ __forceinline__ float blk_max(float v) {
    __shared__ float sh[32];
    int lane = threadIdx.x & 31, w = threadIdx.x >> 5;
#pragma unroll
    for (int o = 16; o; o >>= 1) v = fmaxf(v, __shfl_xor_sync(0xffffffffu, v, o));
    __syncthreads();
    if (lane == 0) sh[w] = v;
    __syncthreads();
    float r = (threadIdx.x < (blockDim.x >> 5)) ? sh[threadIdx.x] : -INFINITY;
    if (w == 0) {
#pragma unroll
        for (int o = 16; o; o >>= 1) r = fmaxf(r, __shfl_xor_sync(0xffffffffu, r, o));
        if (lane == 0) sh[0] = r;
    }
    __syncthreads();
    return sh[0];
}

// ======= row-max kernels (per logical operand row over K) =======
// element (r,k) at src[(z>>3)*szh + (z&7)*szl + r*rs + k*cs]
__global__ __launch_bounds__(256) void rowmax_b(   // cs==1: block per row
    const float* __restrict__ src, ll szh, ll szl, int rs_, int R, int K,
    float* __restrict__ out, int Rsc)
{
    int r = blockIdx.x, z = blockIdx.y;
    const float* s = src + (ll)(z >> 3) * szh + (ll)(z & 7) * szl + (ll)r * rs_;
    float m = 0.f;
    for (int k = threadIdx.x; k < K; k += 256) m = fmaxf(m, fabsf(s[k]));
    m = blk_max(m);
    if (threadIdx.x == 0) out[(ll)z * Rsc + r] = fmaxf(m, 1e-20f);
}
__global__ __launch_bounds__(256) void rowmax_t(   // rs==1: thread per row
    const float* __restrict__ src, ll szh, ll szl, int cs_, int R, int K,
    float* __restrict__ out, int Rsc)
{
    int r = blockIdx.x * 256 + threadIdx.x, z = blockIdx.y;
    if (r >= R) return;
    const float* s = src + (ll)(z >> 3) * szh + (ll)(z & 7) * szl + r;
    float m = 0.f;
    for (int k = 0; k < K; k++) m = fmaxf(m, fabsf(s[(ll)k * cs_]));
    out[(ll)z * Rsc + r] = fmaxf(m, 1e-20f);
}

// ======= fp32 -> int8 (q1,q2) Ozaki split, tiled 128x128B, SW128-swizzled =======
__global__ __launch_bounds__(256) void conv8(
    const float* __restrict__ src, ll szh, ll szl,
    int rs_, int cs_, int R, int C, int RT, int CT,
    int8_t* __restrict__ q1, int8_t* __restrict__ q2,
    const float* __restrict__ scale, int Rsc)
{
    __shared__ float sh[128][65];
    int tile = blockIdx.x;
    int ct = tile % CT, rt = (tile / CT) % RT, z = tile / (CT * RT);
    const float* s = src + (ll)(z >> 3) * szh + (ll)(z & 7) * szl;
    const float* sc = scale + (ll)z * Rsc;
    int r0 = rt * 128, tid = threadIdx.x;
    ll tb = (ll)tile * 16384;
#pragma unroll
    for (int h = 0; h < 2; ++h) {
        int c0 = ct * 128 + h * 64;
        if (rs_ == 1) {
#pragma unroll 4
            for (int it = 0; it < 32; ++it) {
                int e = it * 256 + tid, r = e & 127, c = e >> 7;
                int gr = r0 + r, gc = c0 + c;
                sh[r][c] = (gr < R && gc < C) ? s[(ll)gr + (ll)gc * cs_] : 0.f;
            }
        } else {
#pragma unroll 4
            for (int it = 0; it < 32; ++it) {
                int e = it * 256 + tid, r = e >> 6, c = e & 63;
                int gr = r0 + r, gc = c0 + c;
                sh[r][c] = (gr < R && gc < C) ? s[(ll)gr * rs_ + (ll)gc * cs_] : 0.f;
            }
        }
        __syncthreads();
#pragma unroll
        for (int it = 0; it < 2; ++it) {
            int idx = it * 256 + tid;          // 0..511
            int r = idx >> 2, gi = idx & 3;
            float inv = (r0 + r < R) ? 127.0f / sc[r0 + r] : 0.f;
            uint32_t lb = swz((uint32_t)(r * 128 + h * 64 + gi * 16));
            int8_t v1[16], v2[16];
#pragma unroll
            for (int j = 0; j < 16; ++j) {
                float x = sh[r][gi * 16 + j] * inv;
                float qh = rintf(x);
                v1[j] = (int8_t)(int)qh;
                v2[j] = (int8_t)(int)rintf((x - qh) * 127.0f);
            }
            *(int4*)(q1 + tb + lb) = *(const int4*)v1;
            *(int4*)(q2 + tb + lb) = *(const int4*)v2;
        }
        __syncthreads();
    }
}

// ======= int8 Ozaki GEMM via mma.sync: D = alpha*deq(A@B^T) (+bias)(relu)(*rowScale) =======
// Stage = [Aq1 16K][Aq2 16K][Bq1 16K][Bq2 16K] = 64KB (k-chunk 128), double buffered.
// 256 threads, 8 warps in 2(m) x 4(n); warp tile 64x32.
#define SMEM_DYN (2 * 65536)

__global__ __launch_bounds__(256, 1)
void tgemm(const int8_t* __restrict__ Aq1, const int8_t* __restrict__ Aq2,
           const int8_t* __restrict__ Bq1, const int8_t* __restrict__ Bq2,
           float* __restrict__ C, int Mv, int Nv, int KT,
           ll sAh, ll sAl, ll sBh, ll sBl,
           ll sCh, ll sCl, int ldc, int cstride,
           const float* __restrict__ bias, ll sbh, ll sbl,
           const float* __restrict__ rsc, ll srh, ll srl,
           const float* __restrict__ scA, ll sAzh, ll sAzl,
           const float* __restrict__ scB, ll sBzh, ll sBzl,
           float alpha, int relu)
{
    extern __shared__ __align__(16) char dsm[];
    uint32_t base = smem_u32(dsm);

    int tid = threadIdx.x, wid = tid >> 5, lane = tid & 31;
    int z = blockIdx.z, mt = blockIdx.y, nt = blockIdx.x;
    int zh = z >> 3, zl = z & 7;

    const int8_t* A1 = Aq1 + zh * sAh + zl * sAl + (ll)mt * KT * 16384;
    const int8_t* A2 = Aq2 + zh * sAh + zl * sAl + (ll)mt * KT * 16384;
    const int8_t* B1 = Bq1 + zh * sBh + zl * sBl + (ll)nt * KT * 16384;
    const int8_t* B2 = Bq2 + zh * sBh + zl * sBl + (ll)nt * KT * 16384;

    int warp_m = wid >> 2, warp_n = wid & 3;
    uint32_t aOff = (uint32_t)(warp_m * 64 + (lane & 15)) * 128 + ((lane >> 4) << 4);
    uint32_t bOff = (uint32_t)(warp_n * 32 + (lane & 7) + ((lane >> 4) << 3)) * 128
                  + (((lane >> 3) & 1) << 4);

    int acc1[4][4][4], accx[4][4][4];
#pragma unroll
    for (int i = 0; i < 4; i++)
#pragma unroll
        for (int j = 0; j < 4; j++)
#pragma unroll
            for (int l = 0; l < 4; l++) { acc1[i][j][l] = 0; accx[i][j][l] = 0; }

    // prologue: stage 0 <- chunk 0
    {
        uint32_t so = base;
#pragma unroll
        for (int i = 0; i < 4; ++i) {
            uint32_t off = tid * 16 + i * 4096;
            cpa16(so + off,         A1 + off);
            cpa16(so + 16384 + off, A2 + off);
            cpa16(so + 32768 + off, B1 + off);
            cpa16(so + 49152 + off, B2 + off);
        }
        asm volatile("cp.async.commit_group;" ::: "memory");
    }

    for (int kt = 0; kt < KT; ++kt) {
        int s = kt & 1;
        if (kt + 1 < KT) {
            uint32_t so = base + (s ^ 1) * 65536;
            ll kb = (ll)(kt + 1) * 16384;
#pragma unroll
            for (int i = 0; i < 4; ++i) {
                uint32_t off = tid * 16 + i * 4096;
                cpa16(so + off,         A1 + kb + off);
                cpa16(so + 16384 + off, A2 + kb + off);
                cpa16(so + 32768 + off, B1 + kb + off);
                cpa16(so + 49152 + off, B2 + kb + off);
            }
            asm volatile("cp.async.commit_group;" ::: "memory");
            asm volatile("cp.async.wait_group 1;" ::: "memory");
        } else {
            asm volatile("cp.async.wait_group 0;" ::: "memory");
        }
        __syncthreads();

        uint32_t sb = base + s * 65536;
#pragma unroll
        for (int ks = 0; ks < 4; ++ks) {           // 4 x k32 per 128B row
            uint32_t kb = ks * 32;
            uint32_t a1[4][4], a2[4][4], b1[2][4], b2[2][4];
#pragma unroll
            for (int m = 0; m < 4; ++m) {
                uint32_t o = swz(aOff + m * 2048 + kb);
                ldsm4(a1[m], sb + o);
                ldsm4(a2[m], sb + 16384 + o);
            }
#pragma unroll
            for (int p = 0; p < 2; ++p) {
                uint32_t o = swz(bOff + p * 2048 + kb);
                ldsm4(b1[p], sb + 32768 + o);
                ldsm4(b2[p], sb + 49152 + o);
            }
#pragma unroll
            for (int m = 0; m < 4; ++m)
#pragma unroll
                for (int p = 0; p < 2; ++p)
#pragma unroll
                    for (int sub = 0; sub < 2; ++sub) {
                        int n = p * 2 + sub;
                        imma(acc1[m][n], a1[m], b1[p][sub*2], b1[p][sub*2+1]);
                        imma(accx[m][n], a1[m], b2[p][sub*2], b2[p][sub*2+1]);
                        imma(accx[m][n], a2[m], b1[p][sub*2], b1[p][sub*2+1]);
                    }
        }
        __syncthreads();
    }

    // ---- epilogue: dequant + alpha/bias/relu/rowScale ----
    float* Cp = C + (ll)zh * sCh + (ll)zl * sCl;
    const float* bp = bias ? bias + zh * sbh + zl * sbl : nullptr;
    const float* rp = rsc  ? rsc  + zh * srh + zl * srl : nullptr;
    const float* mAp = scA + zh * sAzh + zl * sAzl;
    const float* mBp = scB + zh * sBzh + zl * sBzl;
    int g = lane >> 2, t4 = lane & 3;
#pragma unroll
    for (int m = 0; m < 4; ++m) {
        int r0 = mt * 128 + warp_m * 64 + m * 16 + g;   // rows r0, r0+8
        float rv0 = 1.f, rv1 = 1.f, mA0 = 0.f, mA1 = 0.f;
        if (r0 < Mv)     { mA0 = mAp[r0];     if (rp) rv0 = rp[r0]; }
        if (r0 + 8 < Mv) { mA1 = mAp[r0 + 8]; if (rp) rv1 = rp[r0 + 8]; }
#pragma unroll
        for (int n = 0; n < 4; ++n) {
            int c0 = nt * 128 + warp_n * 32 + n * 8 + t4 * 2;
#pragma unroll
            for (int e = 0; e < 2; ++e) {
                int col = c0 + e;
                if (col >= Nv) continue;
                float mB = mBp[col];
                float badd = bp ? bp[col] : 0.f;
                if (r0 < Mv) {
                    float k = mA0 * mB * (1.0f / 16129.0f);
                    float v = ((float)acc1[m][n][e] + (float)accx[m][n][e] * (1.0f / 127.0f)) * k;
                    v = v * alpha + badd;
                    if (relu) v = fmaxf(v, 0.f);
                    Cp[(ll)r0 * ldc + (ll)col * cstride] = v * rv0;
                }
                if (r0 + 8 < Mv) {
                    float k = mA1 * mB * (1.0f / 16129.0f);
                    float v = ((float)acc1[m][n][2+e] + (float)accx[m][n][2+e] * (1.0f / 127.0f)) * k;
                    v = v * alpha + badd;
                    if (relu) v = fmaxf(v, 0.f);
                    Cp[(ll)(r0 + 8) * ldc + (ll)col * cstride] = v * rv1;
                }
            }
        }
    }
}

// ---------------- elementwise ----------------
__global__ void concat_kernel(const float* __restrict__ x, const float* __restrict__ l,
                              float* __restrict__ o) {
    int r = blockIdx.x, t = threadIdx.x;
    o[(ll)r * 259 + t] = x[(ll)r * 256 + t];
    if (t < LBL) o[(ll)r * 259 + 256 + t] = l[(ll)r * LBL + t];
}
__global__ void qfeat_kernel(float* __restrict__ dd, const float* __restrict__ q) {
    ll row = blockIdx.x;
    const float* qr = q + row * DD;
    float* d = dd + row * NBF;
    int t = threadIdx.x;
    float qv = qr[t];
    float diag = 0.5f * blk_sum(qv * qv) * DN2;
    float mx = -INFINITY;
    for (int f = t; f < NBF; f += 256) mx = fmaxf(mx, d[f]);
    mx = blk_max(mx);
    float sub = diag + mx;
    for (int f = t; f < NBF; f += 256) d[f] = RATIO * (__expf(d[f] - sub) + EPS_);
}
__global__ void kmax_kernel(const float* __restrict__ dd, float* __restrict__ km) {
    int th = blockIdx.y, ch = blockIdx.x;
    const float* b = dd + ((ll)th * NCC + (ll)ch * 64) * NBF;
    float mx = -INFINITY;
    for (ll i = threadIdx.x; i < (ll)64 * NBF; i += blockDim.x)
        mx = fmaxf(mx, b[i]);
    mx = blk_max(mx);
    if (threadIdx.x == 0) km[th * 8 + ch] = mx;
}
__global__ void kfeat_kernel(float* __restrict__ dd, const float* __restrict__ k,
                             const float* __restrict__ km) {
    ll row = blockIdx.x;
    int th = (int)(row >> 9), t = threadIdx.x;
    const float* kr = k + row * DD;
    float* d = dd + row * NBF;
    float kv = kr[t];
    float diag = 0.5f * blk_sum(kv * kv) * DN2;
    float mx = -INFINITY;
#pragma unroll
    for (int c = 0; c < 8; c++) mx = fmaxf(mx, km[th * 8 + c]);
    float sub = diag + mx;
    for (int f = t; f < NBF; f += 256) d[f] = RATIO * (__expf(d[f] - sub) + EPS_);
}
__global__ void ksum_kernel(const float* __restrict__ kp, float* __restrict__ ks) {
    int th = blockIdx.y, f = blockIdx.x * 128 + threadIdx.x;
    if (f >= NBF) return;
    const float* b = kp + (ll)th * NCC * NBF + f;
    float s = 0.f;
    for (int n = 0; n < NCC; n++) s += b[(ll)n * NBF];
    ks[(ll)th * NBF + f] = s;
}
__global__ void dinv_kernel(const float* __restrict__ qp, const float* __restrict__ ks,
                            float* __restrict__ di) {
    ll row = blockIdx.x;
    int th = (int)(row >> 9);
    const float* qr = qp + row * NBF;
    const float* k = ks + (ll)th * NBF;
    float s = 0.f;
    for (int f = threadIdx.x; f < NBF; f += 256) s += qr[f] * k[f];
    s = blk_sum(s);
    if (threadIdx.x == 0) di[row] = 1.0f / s;
}

// ---------------- host ----------------
static float*  symf(const void* s) { void* p = nullptr; cudaGetSymbolAddress(&p, s); return (float*)p; }
static int8_t* symi(const void* s) { void* p = nullptr; cudaGetSymbolAddress(&p, s); return (int8_t*)p; }

static void rmax(const float* src, ll szh, ll szl, int rs, int cs, int R, int K,
                 float* out, int Rsc, int nb) {
    if (cs == 1) rowmax_b<<<dim3(R, nb), 256>>>(src, szh, szl, rs, R, K, out, Rsc);
    else         rowmax_t<<<dim3((R + 255) / 256, nb), 256>>>(src, szh, szl, cs, R, K, out, Rsc);
}
static void conv(const float* src, ll szh, ll szl, int rs, int cs, int R, int C,
                 int RT, int CT, int8_t* q1, int8_t* q2, const float* sc, int Rsc, int nb) {
    conv8<<<nb * RT * CT, 256>>>(src, szh, szl, rs, cs, R, C, RT, CT, q1, q2, sc, Rsc);
}
static void tg(const int8_t* A1, const int8_t* A2, const int8_t* B1, const int8_t* B2,
               float* C, int Mv, int Nv, int KT, int MT, int NT, int batch,
               ll sAh, ll sAl, ll sBh, ll sBl,
               ll sCh, ll sCl, int ldc, int cstr,
               const float* bias, ll sbh, ll sbl,
               const float* rs, ll srh, ll srl,
               const float* scA, ll sAzh, ll sAzl,
               const float* scB, ll sBzh, ll sBzl,
               float alpha, int relu) {
    dim3 grid(NT, MT, batch);
    tgemm<<<grid, 256, SMEM_DYN>>>(A1, A2, B1, B2, C, Mv, Nv, KT, sAh, sAl, sBh, sBl,
                                   sCh, sCl, ldc, cstr, bias, sbh, sbl, rs, srh, srl,
                                   scA, sAzh, sAzl, scB, sBzh, sBzl, alpha, relu);
}

extern "C" void kernel_launch(void* const* d_in, const int* in_sizes, int n_in,
                              void* d_out, int out_size) {
    (void)in_sizes; (void)n_in; (void)out_size;
    const float* x_ctx = (const float*)d_in[0];
    const float* label = (const float*)d_in[1];
    const float* x_tgt = (const float*)d_in[2];
    const float* W1 = (const float*)d_in[3];  const float* b1 = (const float*)d_in[4];
    const float* W2 = (const float*)d_in[5];  const float* b2 = (const float*)d_in[6];
    const float* W3 = (const float*)d_in[7];  const float* b3 = (const float*)d_in[8];
    const float* Wk = (const float*)d_in[9];  const float* bk = (const float*)d_in[10];
    const float* Wv = (const float*)d_in[11]; const float* bv = (const float*)d_in[12];
    const float* Wq = (const float*)d_in[13]; const float* bq = (const float*)d_in[14];
    const float* Wo = (const float*)d_in[15]; const float* bo = (const float*)d_in[16];
    const float* Wmu = (const float*)d_in[17]; const float* bmu = (const float*)d_in[18];
    const float* proj = (const float*)d_in[19];
    float* out = (float*)d_out;

    cudaFuncSetAttribute(tgemm, cudaFuncAttributeMaxDynamicSharedMemorySize, SMEM_DYN);

    float *xc = symf(g_xc), *h1 = symf(g_h1), *h2 = symf(g_h2), *cf = symf(g_cf);
    float *kb = symf(g_k), *vb = symf(g_v), *qb = symf(g_q);
    float *qp = symf(g_qp), *kp = symf(g_kp), *ksum = symf(g_ksum);
    float *kmxp = symf(g_kmxp), *dinv = symf(g_dinv), *ctx = symf(g_ctx);
    float *om = symf(g_om), *rep = symf(g_rep);
    float *scA = symf(g_scA), *scB = symf(g_scB);
    int8_t *A1 = symi(pAq1), *A2 = symi(pAq2), *B1 = symi(pBq1), *B2 = symi(pBq2);

    // 1) task encoder MLP
    concat_kernel<<<TT * NCC, 256>>>(x_ctx, label, xc);
    rmax(xc, 0, 0, 259, 1, 4096, 259, scA, 4096, 1);
    conv(xc, 0, 0, 259, 1, 4096, 259, 32, 3, A1, A2, scA, 4096, 1);
    rmax(W1, 0, 0, 1, 256, 256, 259, scB, 256, 1);        // B[n,k]=W1[k*256+n]
    conv(W1, 0, 0, 1, 256, 256, 259, 2, 3, B1, B2, scB, 256, 1);
    tg(A1, A2, B1, B2, h1, 4096, 256, 3, 32, 2, 1, 0,0,0,0, 0,0, 256,1,
       b1,0,0, nullptr,0,0, scA,0,0, scB,0,0, 1.f, 1);
    rmax(h1, 0, 0, 256, 1, 4096, 256, scA, 4096, 1);
    conv(h1, 0, 0, 256, 1, 4096, 256, 32, 2, A1, A2, scA, 4096, 1);
    rmax(W2, 0, 0, 1, 256, 256, 256, scB, 256, 1);
    conv(W2, 0, 0, 1, 256, 256, 256, 2, 2, B1, B2, scB, 256, 1);
    tg(A1, A2, B1, B2, h2, 4096, 256, 2, 32, 2, 1, 0,0,0,0, 0,0, 256,1,
       b2,0,0, nullptr,0,0, scA,0,0, scB,0,0, 1.f, 1);
    rmax(h2, 0, 0, 256, 1, 4096, 256, scA, 4096, 1);
    conv(h2, 0, 0, 256, 1, 4096, 256, 32, 2, A1, A2, scA, 4096, 1);
    rmax(W3, 0, 0, 1, 256, 256, 256, scB, 256, 1);
    conv(W3, 0, 0, 1, 256, 256, 256, 2, 2, B1, B2, scB, 256, 1);
    tg(A1, A2, B1, B2, cf, 4096, 256, 2, 32, 2, 1, 0,0,0,0, 0,0, 256,1,
       b3,0,0, nullptr,0,0, scA,0,0, scB,0,0, 1.f, 1);

    // 2) per-head k/v/q projections -> [t,h,n,e]; z = t*8+h
    rmax(x_ctx, 0, 0, 256, 1, 4096, 256, scA, 4096, 1);
    conv(x_ctx, 0, 0, 256, 1, 4096, 256, 32, 2, A1, A2, scA, 4096, 1);
    rmax(Wk, 0, 65536, 1, 256, 256, 256, scB, 256, 8);    // B[n=e,k=d]=Wk[h][d*256+e]
    conv(Wk, 0, 65536, 1, 256, 256, 256, 2, 2, B1, B2, scB, 256, 8);
    tg(A1, A2, B1, B2, kb, 512, 256, 2, 4, 2, 64, 131072,0, 0,65536,
       1048576,131072, 256,1, bk,0,256, nullptr,0,0, scA,512,0, scB,0,256, 1.f, 0);
    rmax(cf, 0, 0, 256, 1, 4096, 256, scA, 4096, 1);
    conv(cf, 0, 0, 256, 1, 4096, 256, 32, 2, A1, A2, scA, 4096, 1);
    rmax(Wv, 0, 65536, 1, 256, 256, 256, scB, 256, 8);
    conv(Wv, 0, 65536, 1, 256, 256, 256, 2, 2, B1, B2, scB, 256, 8);
    tg(A1, A2, B1, B2, vb, 512, 256, 2, 4, 2, 64, 131072,0, 0,65536,
       1048576,131072, 256,1, bv,0,256, nullptr,0,0, scA,512,0, scB,0,256, 1.f, 0);
    rmax(x_tgt, 0, 0, 256, 1, 4096, 256, scA, 4096, 1);
    conv(x_tgt, 0, 0, 256, 1, 4096, 256, 32, 2, A1, A2, scA, 4096, 1);
    rmax(Wq, 0, 65536, 1, 256, 256, 256, scB, 256, 8);
    conv(Wq, 0, 65536, 1, 256, 256, 256, 2, 2, B1, B2, scB, 256, 8);
    tg(A1, A2, B1, B2, qb, 512, 256, 2, 4, 2, 64, 131072,0, 0,65536,
       1048576,131072, 256,1, bq,0,256, nullptr,0,0, scA,512,0, scB,0,256, 1.f, 0);

    // 3) FAVOR+ projections: dd = DN * X @ proj^T
    rmax(proj, 0, 0, 256, 1, 1419, 256, scB, 1419, 1);    // B[n=f,k=d]=proj[f*256+d]
    conv(proj, 0, 0, 256, 1, 1419, 256, 12, 2, B1, B2, scB, 1419, 1);
    rmax(qb, 0, 0, 256, 1, 32768, 256, scA, 32768, 1);
    conv(qb, 0, 0, 256, 1, 32768, 256, 256, 2, A1, A2, scA, 32768, 1);
    tg(A1, A2, B1, B2, qp, 32768, NBF, 2, 256, 12, 1, 0,0,0,0, 0,0, NBF,1,
       nullptr,0,0, nullptr,0,0, scA,0,0, scB,0,0, DN, 0);
    rmax(kb, 0, 0, 256, 1, 32768, 256, scA, 32768, 1);
    conv(kb, 0, 0, 256, 1, 32768, 256, 256, 2, A1, A2, scA, 32768, 1);
    tg(A1, A2, B1, B2, kp, 32768, NBF, 2, 256, 12, 1, 0,0,0,0, 0,0, NBF,1,
       nullptr,0,0, nullptr,0,0, scA,0,0, scB,0,0, DN, 0);

    // 4) softmax-kernel transforms
    kmax_kernel<<<dim3(8, TT * HH), 256>>>(kp, kmxp);
    kfeat_kernel<<<TT * HH * NCC, 256>>>(kp, kb, kmxp);
    qfeat_kernel<<<TT * HH * NTT, 256>>>(qp, qb);
    ksum_kernel<<<dim3(12, TT * HH), 128>>>(kp, ksum);
    dinv_kernel<<<TT * HH * NTT, 256>>>(qp, ksum, dinv);

    // 5) ctx[z] = kp[z]^T @ v[z]   (M=1419, K=512, N=256, 64 batches)
    rmax(kp, 8LL*726528, 726528, 1, 1419, 1419, 512, scA, 1536, 64);     // A[f,n]
    conv(kp, 8LL*726528, 726528, 1, 1419, 1419, 512, 12, 4, A1, A2, scA, 1536, 64);
    rmax(vb, 8LL*131072, 131072, 1, 256, 256, 512, scB, 256, 64);        // B[e,n]
    conv(vb, 8LL*131072, 131072, 1, 256, 256, 512, 2, 4, B1, B2, scB, 256, 64);
    tg(A1, A2, B1, B2, ctx, NBF, 256, 4, 12, 2, 64, 8LL*786432,786432, 8LL*131072,131072,
       8LL*363264,363264, 256,1, nullptr,0,0, nullptr,0,0,
       scA,12288,1536, scB,2048,256, 1.f, 0);

    // 6) om = (qp @ ctx) * dinv, head-interleaved store om[t][n][e*8+h]
    rmax(qp, 8LL*726528, 726528, 1419, 1, 512, 1419, scA, 512, 64);      // A[n,f]
    conv(qp, 8LL*726528, 726528, 1419, 1, 512, 1419, 4, 12, A1, A2, scA, 512, 64);
    rmax(ctx, 8LL*363264, 363264, 1, 256, 256, 1419, scB, 256, 64);      // B[e,f]
    conv(ctx, 8LL*363264, 363264, 1, 256, 256, 1419, 2, 12, B1, B2, scB, 256, 64);
    tg(A1, A2, B1, B2, om, 512, 256, 12, 4, 2, 64, 8LL*786432,786432, 8LL*393216,393216,
       1048576,1, 2048,8, nullptr,0,0, dinv,4096,512,
       scA,4096,512, scB,2048,256, 1.f, 0);

    // 7) rep = om @ Wo + bo ; out = rep @ Wmu + bmu
    rmax(om, 0, 0, 2048, 1, 4096, 2048, scA, 4096, 1);
    conv(om, 0, 0, 2048, 1, 4096, 2048, 32, 16, A1, A2, scA, 4096, 1);
    rmax(Wo, 0, 0, 1, 256, 256, 2048, scB, 256, 1);
    conv(Wo, 0, 0, 1, 256, 256, 2048, 2, 16, B1, B2, scB, 256, 1);
    tg(A1, A2, B1, B2, rep, 4096, 256, 16, 32, 2, 1, 0,0,0,0, 0,0, 256,1,
       bo,0,0, nullptr,0,0, scA,0,0, scB,0,0, 1.f, 0);
    rmax(rep, 0, 0, 256, 1, 4096, 256, scA, 4096, 1);
    conv(rep, 0, 0, 256, 1, 4096, 256, 32, 2, A1, A2, scA, 4096, 1);
    rmax(Wmu, 0, 0, 1, 256, 256, 256, scB, 256, 1);
    conv(Wmu, 0, 0, 1, 256, 256, 256, 2, 2, B1, B2, scB, 256, 1);
    tg(A1, A2, B1, B2, out, 4096, 256, 2, 32, 2, 1, 0,0,0,0, 0,0, 256,1,
       bmu,0,0, nullptr,0,0, scA,0,0, scB,0,0, 1.f, 0);
}

// round 13
// speedup vs baseline: 1.0816x; 1.0816x over previous
#include <cuda_runtime.h>
#include <cuda_bf16.h>
#include <math.h>
#include <stdint.h>

#define TT 8
#define NCC 512
#define NTT 512
#define DD 256
#define HH 8
#define LBL 3
#define NBF 1419
#define EPS_ 1e-4f
#define DN 0.25f
#define DN2 0.0625f
#define RATIO 0.026549364f

typedef long long ll;

// ---------------- fp32 scratch ----------------
__device__ float g_xc[TT*NCC*(DD+LBL)];
__device__ float g_h1[TT*NCC*DD];
__device__ float g_h2[TT*NCC*DD];
__device__ float g_cf[TT*NCC*DD];
__device__ float g_k[TT*HH*NCC*DD];
__device__ float g_v[TT*HH*NCC*DD];
__device__ float g_q[TT*HH*NTT*DD];
__device__ float g_qp[(ll)TT*HH*NTT*NBF];
__device__ float g_kp[(ll)TT*HH*NCC*NBF];
__device__ float g_ksum[TT*HH*NBF];
__device__ float g_kmxp[TT*HH*8];
__device__ float g_dinv[TT*HH*NTT];
__device__ float g_ctx[(ll)TT*HH*NBF*DD];
__device__ float g_om[TT*NTT*HH*DD];
__device__ float g_rep[TT*NTT*DD];
__device__ float g_scA[131072];
__device__ float g_scB[131072];

// ---------------- int8 operand pools (tiles: 128 rows x 128 int8 = 16KB) ----------------
#define PA_SZ 50331648LL
#define PB_SZ 25165824LL
__device__ __align__(16) int8_t pAq1[PA_SZ], pAq2[PA_SZ];
__device__ __align__(16) int8_t pBq1[PB_SZ], pBq2[PB_SZ];

// ---------------- PTX helpers ----------------
__device__ __forceinline__ uint32_t smem_u32(const void* p) {
    uint32_t a;
    asm("{ .reg .u64 t; cvta.to.shared.u64 t, %1; cvt.u32.u64 %0, t; }" : "=r"(a) : "l"(p));
    return a;
}
__device__ __forceinline__ void cpa16(uint32_t s, const void* g) {
    asm volatile("cp.async.cg.shared.global [%0], [%1], 16;" :: "r"(s), "l"(g));
}
__device__ __forceinline__ void ldsm4(uint32_t* r, uint32_t addr) {
    asm volatile("ldmatrix.sync.aligned.m8n8.x4.shared.b16 {%0,%1,%2,%3}, [%4];"
        : "=r"(r[0]), "=r"(r[1]), "=r"(r[2]), "=r"(r[3]) : "r"(addr));
}
__device__ __forceinline__ void imma(int* c, const uint32_t* a, uint32_t b0, uint32_t b1) {
    asm volatile("mma.sync.aligned.m16n8k32.row.col.s32.s8.s8.s32 "
        "{%0,%1,%2,%3}, {%4,%5,%6,%7}, {%8,%9}, {%0,%1,%2,%3};"
        : "+r"(c[0]), "+r"(c[1]), "+r"(c[2]), "+r"(c[3])
        : "r"(a[0]), "r"(a[1]), "r"(a[2]), "r"(a[3]), "r"(b0), "r"(b1));
}
__device__ __forceinline__ uint32_t swz(uint32_t off) {
    return off ^ ((off >> 3) & 0x70);
}

// ---------------- reductions ----------------
__device__ __forceinline__ float blk_sum(float v) {
    __shared__ float sh[32];
    int lane = threadIdx.x & 31, w = threadIdx.x >> 5;
#pragma unroll
    for (int o = 16; o; o >>= 1) v += __shfl_xor_sync(0xffffffffu, v, o);
    __syncthreads();
    if (lane == 0) sh[w] = v;
    __syncthreads();
    float r = (threadIdx.x < (blockDim.x >> 5)) ? sh[threadIdx.x] : 0.f;
    if (w == 0) {
#pragma unroll
        for (int o = 16; o; o >>= 1) r += __shfl_xor_sync(0xffffffffu, r, o);
        if (lane == 0) sh[0] = r;
    }
    __syncthreads();
    return sh[0];
}
__device__ __forceinline__ float blk_max(float v) {
    __shared__ float sh[32];
    int lane = threadIdx.x & 31, w = threadIdx.x >> 5;
#pragma unroll
    for (int o = 16; o; o >>= 1) v = fmaxf(v, __shfl_xor_sync(0xffffffffu, v, o));
    __syncthreads();
    if (lane == 0) sh[w] = v;
    __syncthreads();
    float r = (threadIdx.x < (blockDim.x >> 5)) ? sh[threadIdx.x] : -INFINITY;
    if (w == 0) {
#pragma unroll
        for (int o = 16; o; o >>= 1) r = fmaxf(r, __shfl_xor_sync(0xffffffffu, r, o));
        if (lane == 0) sh[0] = r;
    }
    __syncthreads();
    return sh[0];
}

// ======= row-max: one warp per (z, row) =======
__global__ __launch_bounds__(256) void rowmax_w(
    const float* __restrict__ src, ll szh, ll szl, int rs_, int cs_, int R, int K,
    float* __restrict__ out, int Rsc, int total)   // total = R * nb
{
    int w = (blockIdx.x * 256 + threadIdx.x) >> 5;
    if (w >= total) return;
    int lane = threadIdx.x & 31;
    int z = w / R, r = w - z * R;
    const float* s = src + (ll)(z >> 3) * szh + (ll)(z & 7) * szl + (ll)r * rs_;
    float m = 0.f;
    for (int k = lane; k < K; k += 32) m = fmaxf(m, fabsf(s[(ll)k * cs_]));
#pragma unroll
    for (int o = 16; o; o >>= 1) m = fmaxf(m, __shfl_xor_sync(0xffffffffu, m, o));
    if (lane == 0) out[(ll)z * Rsc + r] = fmaxf(m, 1e-20f);
}

// ======= fp32 -> int8 (q1,q2) Ozaki split, tiled 128x128B, SW128-swizzled =======
__global__ __launch_bounds__(256) void conv8(
    const float* __restrict__ src, ll szh, ll szl,
    int rs_, int cs_, int R, int C, int RT, int CT,
    int8_t* __restrict__ q1, int8_t* __restrict__ q2,
    const float* __restrict__ scale, int Rsc)
{
    __shared__ float sh[128][65];
    int tile = blockIdx.x;
    int ct = tile % CT, rt = (tile / CT) % RT, z = tile / (CT * RT);
    const float* s = src + (ll)(z >> 3) * szh + (ll)(z & 7) * szl;
    const float* sc = scale + (ll)z * Rsc;
    int r0 = rt * 128, tid = threadIdx.x;
    ll tb = (ll)tile * 16384;
#pragma unroll
    for (int h = 0; h < 2; ++h) {
        int c0 = ct * 128 + h * 64;
        if (rs_ == 1) {
#pragma unroll 4
            for (int it = 0; it < 32; ++it) {
                int e = it * 256 + tid, r = e & 127, c = e >> 7;
                int gr = r0 + r, gc = c0 + c;
                sh[r][c] = (gr < R && gc < C) ? s[(ll)gr + (ll)gc * cs_] : 0.f;
            }
        } else {
#pragma unroll 4
            for (int it = 0; it < 32; ++it) {
                int e = it * 256 + tid, r = e >> 6, c = e & 63;
                int gr = r0 + r, gc = c0 + c;
                sh[r][c] = (gr < R && gc < C) ? s[(ll)gr * rs_ + (ll)gc * cs_] : 0.f;
            }
        }
        __syncthreads();
#pragma unroll
        for (int it = 0; it < 2; ++it) {
            int idx = it * 256 + tid;
            int r = idx >> 2, gi = idx & 3;
            float inv = (r0 + r < R) ? 127.0f / sc[r0 + r] : 0.f;
            uint32_t lb = swz((uint32_t)(r * 128 + h * 64 + gi * 16));
            int8_t v1[16], v2[16];
#pragma unroll
            for (int j = 0; j < 16; ++j) {
                float x = sh[r][gi * 16 + j] * inv;
                float qh = rintf(x);
                v1[j] = (int8_t)(int)qh;
                v2[j] = (int8_t)(int)rintf((x - qh) * 127.0f);
            }
            *(int4*)(q1 + tb + lb) = *(const int4*)v1;
            *(int4*)(q2 + tb + lb) = *(const int4*)v2;
        }
        __syncthreads();
    }
}

// ======= int8 Ozaki GEMM: D = alpha*deq(A@B^T) (+bias)(relu)(*rowScale) =======
// 512 threads, 16 warps 4(m)x4(n), warp tile 32x32; double-buffered 64KB stages.
#define SMEM_DYN (2 * 65536)

__global__ __launch_bounds__(512, 1)
void tgemm(const int8_t* __restrict__ Aq1, const int8_t* __restrict__ Aq2,
           const int8_t* __restrict__ Bq1, const int8_t* __restrict__ Bq2,
           float* __restrict__ C, int Mv, int Nv, int KT,
           ll sAh, ll sAl, ll sBh, ll sBl,
           ll sCh, ll sCl, int ldc, int cstride,
           const float* __restrict__ bias, ll sbh, ll sbl,
           const float* __restrict__ rsc, ll srh, ll srl,
           const float* __restrict__ scA, ll sAzh, ll sAzl,
           const float* __restrict__ scB, ll sBzh, ll sBzl,
           float alpha, int relu)
{
    extern __shared__ __align__(16) char dsm[];
    uint32_t base = smem_u32(dsm);

    int tid = threadIdx.x, wid = tid >> 5, lane = tid & 31;
    int z = blockIdx.z, mt = blockIdx.y, nt = blockIdx.x;
    int zh = z >> 3, zl = z & 7;

    const int8_t* A1 = Aq1 + zh * sAh + zl * sAl + (ll)mt * KT * 16384;
    const int8_t* A2 = Aq2 + zh * sAh + zl * sAl + (ll)mt * KT * 16384;
    const int8_t* B1 = Bq1 + zh * sBh + zl * sBl + (ll)nt * KT * 16384;
    const int8_t* B2 = Bq2 + zh * sBh + zl * sBl + (ll)nt * KT * 16384;

    int warp_m = wid >> 2, warp_n = wid & 3;
    uint32_t aOff = (uint32_t)(warp_m * 32 + (lane & 15)) * 128 + ((lane >> 4) << 4);
    uint32_t bOff = (uint32_t)(warp_n * 32 + (lane & 7) + ((lane >> 4) << 3)) * 128
                  + (((lane >> 3) & 1) << 4);

    int acc1[2][4][4], accx[2][4][4];
#pragma unroll
    for (int i = 0; i < 2; i++)
#pragma unroll
        for (int j = 0; j < 4; j++)
#pragma unroll
            for (int l = 0; l < 4; l++) { acc1[i][j][l] = 0; accx[i][j][l] = 0; }

    // prologue: stage 0 <- chunk 0 (512 threads x 16B x 2 = 16KB per operand)
    {
        uint32_t so = base;
#pragma unroll
        for (int i = 0; i < 2; ++i) {
            uint32_t off = tid * 16 + i * 8192;
            cpa16(so + off,         A1 + off);
            cpa16(so + 16384 + off, A2 + off);
            cpa16(so + 32768 + off, B1 + off);
            cpa16(so + 49152 + off, B2 + off);
        }
        asm volatile("cp.async.commit_group;" ::: "memory");
    }

    for (int kt = 0; kt < KT; ++kt) {
        int s = kt & 1;
        if (kt + 1 < KT) {
            uint32_t so = base + (s ^ 1) * 65536;
            ll kb = (ll)(kt + 1) * 16384;
#pragma unroll
            for (int i = 0; i < 2; ++i) {
                uint32_t off = tid * 16 + i * 8192;
                cpa16(so + off,         A1 + kb + off);
                cpa16(so + 16384 + off, A2 + kb + off);
                cpa16(so + 32768 + off, B1 + kb + off);
                cpa16(so + 49152 + off, B2 + kb + off);
            }
            asm volatile("cp.async.commit_group;" ::: "memory");
            asm volatile("cp.async.wait_group 1;" ::: "memory");
        } else {
            asm volatile("cp.async.wait_group 0;" ::: "memory");
        }
        __syncthreads();

        uint32_t sb = base + s * 65536;
#pragma unroll
        for (int ks = 0; ks < 4; ++ks) {
            uint32_t kb = ks * 32;
            uint32_t b1[2][4], b2[2][4];
#pragma unroll
            for (int p = 0; p < 2; ++p) {
                uint32_t o = swz(bOff + p * 2048 + kb);
                ldsm4(b1[p], sb + 32768 + o);
                ldsm4(b2[p], sb + 49152 + o);
            }
#pragma unroll
            for (int m = 0; m < 2; ++m) {
                uint32_t a1[4], a2[4];
                uint32_t o = swz(aOff + m * 2048 + kb);
                ldsm4(a1, sb + o);
                ldsm4(a2, sb + 16384 + o);
#pragma unroll
                for (int p = 0; p < 2; ++p)
#pragma unroll
                    for (int sub = 0; sub < 2; ++sub) {
                        int n = p * 2 + sub;
                        imma(acc1[m][n], a1, b1[p][sub*2], b1[p][sub*2+1]);
                        imma(accx[m][n], a1, b2[p][sub*2], b2[p][sub*2+1]);
                        imma(accx[m][n], a2, b1[p][sub*2], b1[p][sub*2+1]);
                    }
            }
        }
        __syncthreads();
    }

    // ---- epilogue: dequant + alpha/bias/relu/rowScale ----
    float* Cp = C + (ll)zh * sCh + (ll)zl * sCl;
    const float* bp = bias ? bias + zh * sbh + zl * sbl : nullptr;
    const float* rp = rsc  ? rsc  + zh * srh + zl * srl : nullptr;
    const float* mAp = scA + zh * sAzh + zl * sAzl;
    const float* mBp = scB + zh * sBzh + zl * sBzl;
    int g = lane >> 2, t4 = lane & 3;
#pragma unroll
    for (int m = 0; m < 2; ++m) {
        int r0 = mt * 128 + warp_m * 32 + m * 16 + g;
        float rv0 = 1.f, rv1 = 1.f, mA0 = 0.f, mA1 = 0.f;
        if (r0 < Mv)     { mA0 = mAp[r0];     if (rp) rv0 = rp[r0]; }
        if (r0 + 8 < Mv) { mA1 = mAp[r0 + 8]; if (rp) rv1 = rp[r0 + 8]; }
#pragma unroll
        for (int n = 0; n < 4; ++n) {
            int c0 = nt * 128 + warp_n * 32 + n * 8 + t4 * 2;
#pragma unroll
            for (int e = 0; e < 2; ++e) {
                int col = c0 + e;
                if (col >= Nv) continue;
                float mB = mBp[col];
                float badd = bp ? bp[col] : 0.f;
                if (r0 < Mv) {
                    float k = mA0 * mB * (1.0f / 16129.0f);
                    float v = ((float)acc1[m][n][e] + (float)accx[m][n][e] * (1.0f / 127.0f)) * k;
                    v = v * alpha + badd;
                    if (relu) v = fmaxf(v, 0.f);
                    Cp[(ll)r0 * ldc + (ll)col * cstride] = v * rv0;
                }
                if (r0 + 8 < Mv) {
                    float k = mA1 * mB * (1.0f / 16129.0f);
                    float v = ((float)acc1[m][n][2+e] + (float)accx[m][n][2+e] * (1.0f / 127.0f)) * k;
                    v = v * alpha + badd;
                    if (relu) v = fmaxf(v, 0.f);
                    Cp[(ll)(r0 + 8) * ldc + (ll)col * cstride] = v * rv1;
                }
            }
        }
    }
}

// ---------------- elementwise ----------------
__global__ void concat_kernel(const float* __restrict__ x, const float* __restrict__ l,
                              float* __restrict__ o) {
    int r = blockIdx.x, t = threadIdx.x;
    o[(ll)r * 259 + t] = x[(ll)r * 256 + t];
    if (t < LBL) o[(ll)r * 259 + 256 + t] = l[(ll)r * LBL + t];
}
__global__ void qfeat_kernel(float* __restrict__ dd, const float* __restrict__ q) {
    ll row = blockIdx.x;
    const float* qr = q + row * DD;
    float* d = dd + row * NBF;
    int t = threadIdx.x;
    float qv = qr[t];
    float diag = 0.5f * blk_sum(qv * qv) * DN2;
    float mx = -INFINITY;
    for (int f = t; f < NBF; f += 256) mx = fmaxf(mx, d[f]);
    mx = blk_max(mx);
    float sub = diag + mx;
    for (int f = t; f < NBF; f += 256) d[f] = RATIO * (__expf(d[f] - sub) + EPS_);
}
__global__ void kmax_kernel(const float* __restrict__ dd, float* __restrict__ km) {
    int th = blockIdx.y, ch = blockIdx.x;
    const float* b = dd + ((ll)th * NCC + (ll)ch * 64) * NBF;
    float mx = -INFINITY;
    for (ll i = threadIdx.x; i < (ll)64 * NBF; i += blockDim.x)
        mx = fmaxf(mx, b[i]);
    mx = blk_max(mx);
    if (threadIdx.x == 0) km[th * 8 + ch] = mx;
}
__global__ void kfeat_kernel(float* __restrict__ dd, const float* __restrict__ k,
                             const float* __restrict__ km) {
    ll row = blockIdx.x;
    int th = (int)(row >> 9), t = threadIdx.x;
    const float* kr = k + row * DD;
    float* d = dd + row * NBF;
    float kv = kr[t];
    float diag = 0.5f * blk_sum(kv * kv) * DN2;
    float mx = -INFINITY;
#pragma unroll
    for (int c = 0; c < 8; c++) mx = fmaxf(mx, km[th * 8 + c]);
    float sub = diag + mx;
    for (int f = t; f < NBF; f += 256) d[f] = RATIO * (__expf(d[f] - sub) + EPS_);
}
__global__ void ksum_kernel(const float* __restrict__ kp, float* __restrict__ ks) {
    int th = blockIdx.y, f = blockIdx.x * 128 + threadIdx.x;
    if (f >= NBF) return;
    const float* b = kp + (ll)th * NCC * NBF + f;
    float s = 0.f;
    for (int n = 0; n < NCC; n++) s += b[(ll)n * NBF];
    ks[(ll)th * NBF + f] = s;
}
__global__ void dinv_kernel(const float* __restrict__ qp, const float* __restrict__ ks,
                            float* __restrict__ di) {
    ll row = blockIdx.x;
    int th = (int)(row >> 9);
    const float* qr = qp + row * NBF;
    const float* k = ks + (ll)th * NBF;
    float s = 0.f;
    for (int f = threadIdx.x; f < NBF; f += 256) s += qr[f] * k[f];
    s = blk_sum(s);
    if (threadIdx.x == 0) di[row] = 1.0f / s;
}

// ---------------- host ----------------
static float*  symf(const void* s) { void* p = nullptr; cudaGetSymbolAddress(&p, s); return (float*)p; }
static int8_t* symi(const void* s) { void* p = nullptr; cudaGetSymbolAddress(&p, s); return (int8_t*)p; }

static void rmax(const float* src, ll szh, ll szl, int rs, int cs, int R, int K,
                 float* out, int Rsc, int nb) {
    int total = R * nb;
    rowmax_w<<<(total + 7) / 8, 256>>>(src, szh, szl, rs, cs, R, K, out, Rsc, total);
}
static void conv(const float* src, ll szh, ll szl, int rs, int cs, int R, int C,
                 int RT, int CT, int8_t* q1, int8_t* q2, const float* sc, int Rsc, int nb) {
    conv8<<<nb * RT * CT, 256>>>(src, szh, szl, rs, cs, R, C, RT, CT, q1, q2, sc, Rsc);
}
static void tg(const int8_t* A1, const int8_t* A2, const int8_t* B1, const int8_t* B2,
               float* C, int Mv, int Nv, int KT, int MT, int NT, int batch,
               ll sAh, ll sAl, ll sBh, ll sBl,
               ll sCh, ll sCl, int ldc, int cstr,
               const float* bias, ll sbh, ll sbl,
               const float* rs, ll srh, ll srl,
               const float* scA, ll sAzh, ll sAzl,
               const float* scB, ll sBzh, ll sBzl,
               float alpha, int relu) {
    dim3 grid(NT, MT, batch);
    tgemm<<<grid, 512, SMEM_DYN>>>(A1, A2, B1, B2, C, Mv, Nv, KT, sAh, sAl, sBh, sBl,
                                   sCh, sCl, ldc, cstr, bias, sbh, sbl, rs, srh, srl,
                                   scA, sAzh, sAzl, scB, sBzh, sBzl, alpha, relu);
}

extern "C" void kernel_launch(void* const* d_in, const int* in_sizes, int n_in,
                              void* d_out, int out_size) {
    (void)in_sizes; (void)n_in; (void)out_size;
    const float* x_ctx = (const float*)d_in[0];
    const float* label = (const float*)d_in[1];
    const float* x_tgt = (const float*)d_in[2];
    const float* W1 = (const float*)d_in[3];  const float* b1 = (const float*)d_in[4];
    const float* W2 = (const float*)d_in[5];  const float* b2 = (const float*)d_in[6];
    const float* W3 = (const float*)d_in[7];  const float* b3 = (const float*)d_in[8];
    const float* Wk = (const float*)d_in[9];  const float* bk = (const float*)d_in[10];
    const float* Wv = (const float*)d_in[11]; const float* bv = (const float*)d_in[12];
    const float* Wq = (const float*)d_in[13]; const float* bq = (const float*)d_in[14];
    const float* Wo = (const float*)d_in[15]; const float* bo = (const float*)d_in[16];
    const float* Wmu = (const float*)d_in[17]; const float* bmu = (const float*)d_in[18];
    const float* proj = (const float*)d_in[19];
    float* out = (float*)d_out;

    cudaFuncSetAttribute(tgemm, cudaFuncAttributeMaxDynamicSharedMemorySize, SMEM_DYN);

    float *xc = symf(g_xc), *h1 = symf(g_h1), *h2 = symf(g_h2), *cf = symf(g_cf);
    float *kb = symf(g_k), *vb = symf(g_v), *qb = symf(g_q);
    float *qp = symf(g_qp), *kp = symf(g_kp), *ksum = symf(g_ksum);
    float *kmxp = symf(g_kmxp), *dinv = symf(g_dinv), *ctx = symf(g_ctx);
    float *om = symf(g_om), *rep = symf(g_rep);
    float *scA = symf(g_scA), *scB = symf(g_scB);
    int8_t *A1 = symi(pAq1), *A2 = symi(pAq2), *B1 = symi(pBq1), *B2 = symi(pBq2);

    // 1) task encoder MLP
    concat_kernel<<<TT * NCC, 256>>>(x_ctx, label, xc);
    rmax(xc, 0, 0, 259, 1, 4096, 259, scA, 4096, 1);
    conv(xc, 0, 0, 259, 1, 4096, 259, 32, 3, A1, A2, scA, 4096, 1);
    rmax(W1, 0, 0, 1, 256, 256, 259, scB, 256, 1);
    conv(W1, 0, 0, 1, 256, 256, 259, 2, 3, B1, B2, scB, 256, 1);
    tg(A1, A2, B1, B2, h1, 4096, 256, 3, 32, 2, 1, 0,0,0,0, 0,0, 256,1,
       b1,0,0, nullptr,0,0, scA,0,0, scB,0,0, 1.f, 1);
    rmax(h1, 0, 0, 256, 1, 4096, 256, scA, 4096, 1);
    conv(h1, 0, 0, 256, 1, 4096, 256, 32, 2, A1, A2, scA, 4096, 1);
    rmax(W2, 0, 0, 1, 256, 256, 256, scB, 256, 1);
    conv(W2, 0, 0, 1, 256, 256, 256, 2, 2, B1, B2, scB, 256, 1);
    tg(A1, A2, B1, B2, h2, 4096, 256, 2, 32, 2, 1, 0,0,0,0, 0,0, 256,1,
       b2,0,0, nullptr,0,0, scA,0,0, scB,0,0, 1.f, 1);
    rmax(h2, 0, 0, 256, 1, 4096, 256, scA, 4096, 1);
    conv(h2, 0, 0, 256, 1, 4096, 256, 32, 2, A1, A2, scA, 4096, 1);
    rmax(W3, 0, 0, 1, 256, 256, 256, scB, 256, 1);
    conv(W3, 0, 0, 1, 256, 256, 256, 2, 2, B1, B2, scB, 256, 1);
    tg(A1, A2, B1, B2, cf, 4096, 256, 2, 32, 2, 1, 0,0,0,0, 0,0, 256,1,
       b3,0,0, nullptr,0,0, scA,0,0, scB,0,0, 1.f, 1);

    // 2) per-head k/v/q projections -> [t,h,n,e]; z = t*8+h
    rmax(x_ctx, 0, 0, 256, 1, 4096, 256, scA, 4096, 1);
    conv(x_ctx, 0, 0, 256, 1, 4096, 256, 32, 2, A1, A2, scA, 4096, 1);
    rmax(Wk, 0, 65536, 1, 256, 256, 256, scB, 256, 8);
    conv(Wk, 0, 65536, 1, 256, 256, 256, 2, 2, B1, B2, scB, 256, 8);
    tg(A1, A2, B1, B2, kb, 512, 256, 2, 4, 2, 64, 131072,0, 0,65536,
       1048576,131072, 256,1, bk,0,256, nullptr,0,0, scA,512,0, scB,0,256, 1.f, 0);
    rmax(cf, 0, 0, 256, 1, 4096, 256, scA, 4096, 1);
    conv(cf, 0, 0, 256, 1, 4096, 256, 32, 2, A1, A2, scA, 4096, 1);
    rmax(Wv, 0, 65536, 1, 256, 256, 256, scB, 256, 8);
    conv(Wv, 0, 65536, 1, 256, 256, 256, 2, 2, B1, B2, scB, 256, 8);
    tg(A1, A2, B1, B2, vb, 512, 256, 2, 4, 2, 64, 131072,0, 0,65536,
       1048576,131072, 256,1, bv,0,256, nullptr,0,0, scA,512,0, scB,0,256, 1.f, 0);
    rmax(x_tgt, 0, 0, 256, 1, 4096, 256, scA, 4096, 1);
    conv(x_tgt, 0, 0, 256, 1, 4096, 256, 32, 2, A1, A2, scA, 4096, 1);
    rmax(Wq, 0, 65536, 1, 256, 256, 256, scB, 256, 8);
    conv(Wq, 0, 65536, 1, 256, 256, 256, 2, 2, B1, B2, scB, 256, 8);
    tg(A1, A2, B1, B2, qb, 512, 256, 2, 4, 2, 64, 131072,0, 0,65536,
       1048576,131072, 256,1, bq,0,256, nullptr,0,0, scA,512,0, scB,0,256, 1.f, 0);

    // 3) FAVOR+ projections: dd = DN * X @ proj^T
    rmax(proj, 0, 0, 256, 1, 1419, 256, scB, 1419, 1);
    conv(proj, 0, 0, 256, 1, 1419, 256, 12, 2, B1, B2, scB, 1419, 1);
    rmax(qb, 0, 0, 256, 1, 32768, 256, scA, 32768, 1);
    conv(qb, 0, 0, 256, 1, 32768, 256, 256, 2, A1, A2, scA, 32768, 1);
    tg(A1, A2, B1, B2, qp, 32768, NBF, 2, 256, 12, 1, 0,0,0,0, 0,0, NBF,1,
       nullptr,0,0, nullptr,0,0, scA,0,0, scB,0,0, DN, 0);
    rmax(kb, 0, 0, 256, 1, 32768, 256, scA, 32768, 1);
    conv(kb, 0, 0, 256, 1, 32768, 256, 256, 2, A1, A2, scA, 32768, 1);
    tg(A1, A2, B1, B2, kp, 32768, NBF, 2, 256, 12, 1, 0,0,0,0, 0,0, NBF,1,
       nullptr,0,0, nullptr,0,0, scA,0,0, scB,0,0, DN, 0);

    // 4) softmax-kernel transforms
    kmax_kernel<<<dim3(8, TT * HH), 256>>>(kp, kmxp);
    kfeat_kernel<<<TT * HH * NCC, 256>>>(kp, kb, kmxp);
    qfeat_kernel<<<TT * HH * NTT, 256>>>(qp, qb);
    ksum_kernel<<<dim3(12, TT * HH), 128>>>(kp, ksum);
    dinv_kernel<<<TT * HH * NTT, 256>>>(qp, ksum, dinv);

    // 5) ctx[z] = kp[z]^T @ v[z]   (M=1419, K=512, N=256, 64 batches)
    rmax(kp, 8LL*726528, 726528, 1, 1419, 1419, 512, scA, 1536, 64);
    conv(kp, 8LL*726528, 726528, 1, 1419, 1419, 512, 12, 4, A1, A2, scA, 1536, 64);
    rmax(vb, 8LL*131072, 131072, 1, 256, 256, 512, scB, 256, 64);
    conv(vb, 8LL*131072, 131072, 1, 256, 256, 512, 2, 4, B1, B2, scB, 256, 64);
    tg(A1, A2, B1, B2, ctx, NBF, 256, 4, 12, 2, 64, 8LL*786432,786432, 8LL*131072,131072,
       8LL*363264,363264, 256,1, nullptr,0,0, nullptr,0,0,
       scA,12288,1536, scB,2048,256, 1.f, 0);

    // 6) om = (qp @ ctx) * dinv, head-interleaved store om[t][n][e*8+h]
    rmax(qp, 8LL*726528, 726528, 1419, 1, 512, 1419, scA, 512, 64);
    conv(qp, 8LL*726528, 726528, 1419, 1, 512, 1419, 4, 12, A1, A2, scA, 512, 64);
    rmax(ctx, 8LL*363264, 363264, 1, 256, 256, 1419, scB, 256, 64);
    conv(ctx, 8LL*363264, 363264, 1, 256, 256, 1419, 2, 12, B1, B2, scB, 256, 64);
    tg(A1, A2, B1, B2, om, 512, 256, 12, 4, 2, 64, 8LL*786432,786432, 8LL*393216,393216,
       1048576,1, 2048,8, nullptr,0,0, dinv,4096,512,
       scA,4096,512, scB,2048,256, 1.f, 0);

    // 7) rep = om @ Wo + bo ; out = rep @ Wmu + bmu
    rmax(om, 0, 0, 2048, 1, 4096, 2048, scA, 4096, 1);
    conv(om, 0, 0, 2048, 1, 4096, 2048, 32, 16, A1, A2, scA, 4096, 1);
    rmax(Wo, 0, 0, 1, 256, 256, 2048, scB, 256, 1);
    conv(Wo, 0, 0, 1, 256, 256, 2048, 2, 16, B1, B2, scB, 256, 1);
    tg(A1, A2, B1, B2, rep, 4096, 256, 16, 32, 2, 1, 0,0,0,0, 0,0, 256,1,
       bo,0,0, nullptr,0,0, scA,0,0, scB,0,0, 1.f, 0);
    rmax(rep, 0, 0, 256, 1, 4096, 256, scA, 4096, 1);
    conv(rep, 0, 0, 256, 1, 4096, 256, 32, 2, A1, A2, scA, 4096, 1);
    rmax(Wmu, 0, 0, 1, 256, 256, 256, scB, 256, 1);
    conv(Wmu, 0, 0, 1, 256, 256, 256, 2, 2, B1, B2, scB, 256, 1);
    tg(A1, A2, B1, B2, out, 4096, 256, 2, 32, 2, 1, 0,0,0,0, 0,0, 256,1,
       bmu,0,0, nullptr,0,0, scA,0,0, scB,0,0, 1.f, 0);
}

// round 15
// speedup vs baseline: 2.3758x; 2.1966x over previous
#include <cuda_runtime.h>
#include <cuda_fp16.h>
#include <math.h>
#include <stdint.h>

#define TT 8
#define NCC 512
#define NTT 512
#define DD 256
#define HH 8
#define LBL 3
#define NBF 1419
#define EPS_ 1e-4f
#define DN 0.25f
#define DN2 0.0625f
#define RATIO 0.026549364f
#define LSC 2048.0f
#define ILSC (1.0f / 2048.0f)

typedef __half hf;

// ---------------- fp32 scratch ----------------
__device__ float g_xc[TT*NCC*(DD+LBL)];
__device__ float g_h1[TT*NCC*DD];
__device__ float g_h2[TT*NCC*DD];
__device__ float g_cf[TT*NCC*DD];
__device__ float g_k[TT*HH*NCC*DD];
__device__ float g_v[TT*HH*NCC*DD];
__device__ float g_q[TT*HH*NTT*DD];
__device__ float g_qp[(long long)TT*HH*NTT*NBF];
__device__ float g_kp[(long long)TT*HH*NCC*NBF];
__device__ float g_ksum[TT*HH*NBF];
__device__ float g_kmxp[TT*HH*8];
__device__ float g_dinv[TT*HH*NTT];
__device__ float g_ctx[(long long)TT*HH*NBF*DD];
__device__ float g_om[TT*NTT*HH*DD];
__device__ float g_rep[TT*NTT*DD];

// ---------------- fp16 operand pools (reused across phases) ----------------
#define PA_SZ 50331648LL
#define PB_SZ 24117248LL
__device__ __align__(16) hf pAh[PA_SZ], pAl[PA_SZ];
__device__ __align__(16) hf pBh[PB_SZ], pBl[PB_SZ];

// ---------------- PTX helpers ----------------
__device__ __forceinline__ uint32_t smem_u32(const void* p) {
    uint32_t a;
    asm("{ .reg .u64 t; cvta.to.shared.u64 t, %1; cvt.u32.u64 %0, t; }" : "=r"(a) : "l"(p));
    return a;
}
__device__ __forceinline__ void cpa16(uint32_t s, const void* g) {
    asm volatile("cp.async.cg.shared.global [%0], [%1], 16;" :: "r"(s), "l"(g));
}
__device__ __forceinline__ void ldsm4(uint32_t* r, uint32_t addr) {
    asm volatile("ldmatrix.sync.aligned.m8n8.x4.shared.b16 {%0,%1,%2,%3}, [%4];"
        : "=r"(r[0]), "=r"(r[1]), "=r"(r[2]), "=r"(r[3]) : "r"(addr));
}
// fp16 inputs, fp32 accumulate (main term)
__device__ __forceinline__ void mmaF(float* c, const uint32_t* a, uint32_t b0, uint32_t b1) {
    asm volatile("mma.sync.aligned.m16n8k16.row.col.f32.f16.f16.f32 "
        "{%0,%1,%2,%3}, {%4,%5,%6,%7}, {%8,%9}, {%0,%1,%2,%3};"
        : "+f"(c[0]), "+f"(c[1]), "+f"(c[2]), "+f"(c[3])
        : "r"(a[0]), "r"(a[1]), "r"(a[2]), "r"(a[3]), "r"(b0), "r"(b1));
}
// fp16 inputs, fp16 accumulate (correction terms, lo pre-scaled by 2^11)
__device__ __forceinline__ void mmaH(uint32_t* c, const uint32_t* a, uint32_t b0, uint32_t b1) {
    asm volatile("mma.sync.aligned.m16n8k16.row.col.f16.f16.f16.f16 "
        "{%0,%1}, {%2,%3,%4,%5}, {%6,%7}, {%0,%1};"
        : "+r"(c[0]), "+r"(c[1])
        : "r"(a[0]), "r"(a[1]), "r"(a[2]), "r"(a[3]), "r"(b0), "r"(b1));
}
__device__ __forceinline__ uint32_t swz(uint32_t off) {
    return off ^ ((off >> 3) & 0x70);
}

// ======= fp32 -> (hi, lo*2^11) fp16, tiled 128x64, SW128-swizzled =======
__global__ __launch_bounds__(256) void conv_kernel(
    const float* __restrict__ src, long long szh, long long szl,
    int rs_, int cs_, int R, int C, int RT, int CT,
    hf* __restrict__ hi, hf* __restrict__ lo)
{
    __shared__ float sh[128][65];
    int tile = blockIdx.x;
    int ct = tile % CT, rt = (tile / CT) % RT, z = tile / (CT * RT);
    const float* s = src + (long long)(z >> 3) * szh + (long long)(z & 7) * szl;
    int r0 = rt * 128, c0 = ct * 64, tid = threadIdx.x;
    if (rs_ == 1) {
#pragma unroll 4
        for (int it = 0; it < 32; ++it) {
            int e = it * 256 + tid, r = e & 127, c = e >> 7;
            int gr = r0 + r, gc = c0 + c;
            sh[r][c] = (gr < R && gc < C) ? s[(long long)gr + (long long)gc * cs_] : 0.f;
        }
    } else {
#pragma unroll 4
        for (int it = 0; it < 32; ++it) {
            int e = it * 256 + tid, r = e >> 6, c = e & 63;
            int gr = r0 + r, gc = c0 + c;
            sh[r][c] = (gr < R && gc < C) ? s[(long long)gr * rs_ + (long long)gc * cs_] : 0.f;
        }
    }
    __syncthreads();
    long long tb = (long long)tile * 8192;
#pragma unroll
    for (int it = 0; it < 4; ++it) {
        int p0 = (it * 256 + tid) * 8;
        uint32_t lb = swz((uint32_t)(p0 * 2));
        int q0 = lb >> 1, r = q0 >> 6, c = q0 & 63;
        hf hv[8], lv[8];
#pragma unroll
        for (int j = 0; j < 8; ++j) {
            float x = sh[r][c + j];
            hf h = __float2half(x);
            hv[j] = h;
            lv[j] = __float2half((x - __half2float(h)) * LSC);  // scaled: no fp16 denormals
        }
        *(uint4*)(hi + tb + p0) = *(const uint4*)hv;
        *(uint4*)(lo + tb + p0) = *(const uint4*)lv;
    }
}

// ======= split-fp16 GEMM: D = alpha*A@B^T (+bias)(relu)(*rowScale) =======
// Main: f32-acc; corrections (Ah*Bl + Al*Bh, lo scaled 2^11): f16-acc, unscaled in epilogue.
#define SMEM_DYN (2 * 65536)

__global__ __launch_bounds__(256, 1)
void tgemm(const hf* __restrict__ Ahi, const hf* __restrict__ Alo,
           const hf* __restrict__ Bhi, const hf* __restrict__ Blo,
           float* __restrict__ C, int Mv, int Nv, int KT,
           long long sAh, long long sAl, long long sBh, long long sBl,
           long long sCh, long long sCl, int ldc, int cstride,
           const float* __restrict__ bias, long long sbh, long long sbl,
           const float* __restrict__ rsc, long long srh, long long srl,
           float alpha, int relu)
{
    extern __shared__ __align__(16) char dsm[];
    uint32_t base = smem_u32(dsm);

    int tid = threadIdx.x, wid = tid >> 5, lane = tid & 31;
    int z = blockIdx.z, mt = blockIdx.y, nt = blockIdx.x;
    int zh = z >> 3, zl = z & 7;

    const char* Ah = (const char*)(Ahi + zh * sAh + zl * sAl + (long long)mt * KT * 8192);
    const char* Al = (const char*)(Alo + zh * sAh + zl * sAl + (long long)mt * KT * 8192);
    const char* Bh = (const char*)(Bhi + zh * sBh + zl * sBl + (long long)nt * KT * 8192);
    const char* Bl = (const char*)(Blo + zh * sBh + zl * sBl + (long long)nt * KT * 8192);

    int warp_m = wid >> 2, warp_n = wid & 3;
    uint32_t aOff = (uint32_t)(warp_m * 64 + (lane & 15)) * 128 + ((lane >> 4) << 4);
    uint32_t bOff = (uint32_t)(warp_n * 32 + (lane & 7) + ((lane >> 4) << 3)) * 128
                  + (((lane >> 3) & 1) << 4);

    float accF[4][4][4];
    uint32_t accH[4][4][2];
#pragma unroll
    for (int i = 0; i < 4; i++)
#pragma unroll
        for (int j = 0; j < 4; j++) {
#pragma unroll
            for (int l = 0; l < 4; l++) accF[i][j][l] = 0.f;
            accH[i][j][0] = 0u; accH[i][j][1] = 0u;
        }

    // prologue: stage 0 <- chunk 0
    {
        uint32_t so = base;
#pragma unroll
        for (int i = 0; i < 4; ++i) {
            uint32_t off = tid * 16 + i * 4096;
            cpa16(so + off,         Ah + off);
            cpa16(so + 16384 + off, Al + off);
            cpa16(so + 32768 + off, Bh + off);
            cpa16(so + 49152 + off, Bl + off);
        }
        asm volatile("cp.async.commit_group;" ::: "memory");
    }

    for (int kt = 0; kt < KT; ++kt) {
        int s = kt & 1;
        if (kt + 1 < KT) {
            uint32_t so = base + (s ^ 1) * 65536;
            long long kb = (long long)(kt + 1) * 16384;
#pragma unroll
            for (int i = 0; i < 4; ++i) {
                uint32_t off = tid * 16 + i * 4096;
                cpa16(so + off,         Ah + kb + off);
                cpa16(so + 16384 + off, Al + kb + off);
                cpa16(so + 32768 + off, Bh + kb + off);
                cpa16(so + 49152 + off, Bl + kb + off);
            }
            asm volatile("cp.async.commit_group;" ::: "memory");
            asm volatile("cp.async.wait_group 1;" ::: "memory");
        } else {
            asm volatile("cp.async.wait_group 0;" ::: "memory");
        }
        __syncthreads();

        uint32_t sb = base + s * 65536;
#pragma unroll
        for (int ks = 0; ks < 4; ++ks) {
            uint32_t kb = ks * 32;
            uint32_t a_h[4][4], a_l[4][4], b_h[2][4], b_l[2][4];
#pragma unroll
            for (int m = 0; m < 4; ++m) {
                uint32_t o = swz(aOff + m * 2048 + kb);
                ldsm4(a_h[m], sb + o);
                ldsm4(a_l[m], sb + 16384 + o);
            }
#pragma unroll
            for (int p = 0; p < 2; ++p) {
                uint32_t o = swz(bOff + p * 2048 + kb);
                ldsm4(b_h[p], sb + 32768 + o);
                ldsm4(b_l[p], sb + 49152 + o);
            }
#pragma unroll
            for (int m = 0; m < 4; ++m)
#pragma unroll
                for (int p = 0; p < 2; ++p)
#pragma unroll
                    for (int sub = 0; sub < 2; ++sub) {
                        int n = p * 2 + sub;
                        mmaF(accF[m][n], a_h[m], b_h[p][sub*2], b_h[p][sub*2+1]);
                        mmaH(accH[m][n], a_h[m], b_l[p][sub*2], b_l[p][sub*2+1]);
                        mmaH(accH[m][n], a_l[m], b_h[p][sub*2], b_h[p][sub*2+1]);
                    }
        }
        __syncthreads();
    }

    // ---- epilogue: combine f32 main + (f16 corrections) * 2^-11 ----
    float* Cp = C + (long long)zh * sCh + (long long)zl * sCl;
    const float* bp = bias ? bias + zh * sbh + zl * sbl : nullptr;
    const float* rp = rsc  ? rsc  + zh * srh + zl * srl : nullptr;
    int g = lane >> 2, t4 = lane & 3;
#pragma unroll
    for (int m = 0; m < 4; ++m) {
        int r0 = mt * 128 + warp_m * 64 + m * 16 + g;
        float rv0 = (rp && r0     < Mv) ? rp[r0]     : 1.f;
        float rv1 = (rp && r0 + 8 < Mv) ? rp[r0 + 8] : 1.f;
#pragma unroll
        for (int n = 0; n < 4; ++n) {
            int c0 = nt * 128 + warp_n * 32 + n * 8 + t4 * 2;
            __half2 h0 = *reinterpret_cast<const __half2*>(&accH[m][n][0]);
            __half2 h1 = *reinterpret_cast<const __half2*>(&accH[m][n][1]);
            float corr[4] = { __low2float(h0) * ILSC, __high2float(h0) * ILSC,
                              __low2float(h1) * ILSC, __high2float(h1) * ILSC };
#pragma unroll
            for (int e = 0; e < 2; ++e) {
                int col = c0 + e;
                if (col >= Nv) continue;
                float badd = bp ? bp[col] : 0.f;
                if (r0 < Mv) {
                    float v = (accF[m][n][e] + corr[e]) * alpha + badd;
                    if (relu) v = fmaxf(v, 0.f);
                    Cp[(long long)r0 * ldc + (long long)col * cstride] = v * rv0;
                }
                if (r0 + 8 < Mv) {
                    float v = (accF[m][n][2 + e] + corr[2 + e]) * alpha + badd;
                    if (relu) v = fmaxf(v, 0.f);
                    Cp[(long long)(r0 + 8) * ldc + (long long)col * cstride] = v * rv1;
                }
            }
        }
    }
}

// ---------------- reductions ----------------
__device__ __forceinline__ float blk_sum(float v) {
    __shared__ float sh[32];
    int lane = threadIdx.x & 31, w = threadIdx.x >> 5;
#pragma unroll
    for (int o = 16; o; o >>= 1) v += __shfl_xor_sync(0xffffffffu, v, o);
    __syncthreads();
    if (lane == 0) sh[w] = v;
    __syncthreads();
    float r = (threadIdx.x < (blockDim.x >> 5)) ? sh[threadIdx.x] : 0.f;
    if (w == 0) {
#pragma unroll
        for (int o = 16; o; o >>= 1) r += __shfl_xor_sync(0xffffffffu, r, o);
        if (lane == 0) sh[0] = r;
    }
    __syncthreads();
    return sh[0];
}
__device__ __forceinline__ float blk_max(float v) {
    __shared__ float sh[32];
    int lane = threadIdx.x & 31, w = threadIdx.x >> 5;
#pragma unroll
    for (int o = 16; o; o >>= 1) v = fmaxf(v, __shfl_xor_sync(0xffffffffu, v, o));
    __syncthreads();
    if (lane == 0) sh[w] = v;
    __syncthreads();
    float r = (threadIdx.x < (blockDim.x >> 5)) ? sh[threadIdx.x] : -INFINITY;
    if (w == 0) {
#pragma unroll
        for (int o = 16; o; o >>= 1) r = fmaxf(r, __shfl_xor_sync(0xffffffffu, r, o));
        if (lane == 0) sh[0] = r;
    }
    __syncthreads();
    return sh[0];
}

// ---------------- elementwise ----------------
__global__ void concat_kernel(const float* __restrict__ x, const float* __restrict__ l,
                              float* __restrict__ o) {
    int r = blockIdx.x, t = threadIdx.x;
    o[(long long)r * 259 + t] = x[(long long)r * 256 + t];
    if (t < LBL) o[(long long)r * 259 + 256 + t] = l[(long long)r * LBL + t];
}
__global__ void qfeat_kernel(float* __restrict__ dd, const float* __restrict__ q) {
    long long row = blockIdx.x;
    const float* qr = q + row * DD;
    float* d = dd + row * NBF;
    int t = threadIdx.x;
    float qv = qr[t];
    float diag = 0.5f * blk_sum(qv * qv) * DN2;
    float mx = -INFINITY;
    for (int f = t; f < NBF; f += 256) mx = fmaxf(mx, d[f]);
    mx = blk_max(mx);
    float sub = diag + mx;
    for (int f = t; f < NBF; f += 256) d[f] = RATIO * (__expf(d[f] - sub) + EPS_);
}
__global__ void kmax_kernel(const float* __restrict__ dd, float* __restrict__ km) {
    int th = blockIdx.y, ch = blockIdx.x;
    const float* b = dd + ((long long)th * NCC + (long long)ch * 64) * NBF;
    float mx = -INFINITY;
    for (long long i = threadIdx.x; i < (long long)64 * NBF; i += blockDim.x)
        mx = fmaxf(mx, b[i]);
    mx = blk_max(mx);
    if (threadIdx.x == 0) km[th * 8 + ch] = mx;
}
__global__ void kfeat_kernel(float* __restrict__ dd, const float* __restrict__ k,
                             const float* __restrict__ km) {
    long long row = blockIdx.x;
    int th = (int)(row >> 9), t = threadIdx.x;
    const float* kr = k + row * DD;
    float* d = dd + row * NBF;
    float kv = kr[t];
    float diag = 0.5f * blk_sum(kv * kv) * DN2;
    float mx = -INFINITY;
#pragma unroll
    for (int c = 0; c < 8; c++) mx = fmaxf(mx, km[th * 8 + c]);
    float sub = diag + mx;
    for (int f = t; f < NBF; f += 256) d[f] = RATIO * (__expf(d[f] - sub) + EPS_);
}
__global__ void ksum_kernel(const float* __restrict__ kp, float* __restrict__ ks) {
    int th = blockIdx.y, f = blockIdx.x * 128 + threadIdx.x;
    if (f >= NBF) return;
    const float* b = kp + (long long)th * NCC * NBF + f;
    float s = 0.f;
    for (int n = 0; n < NCC; n++) s += b[(long long)n * NBF];
    ks[(long long)th * NBF + f] = s;
}
__global__ void dinv_kernel(const float* __restrict__ qp, const float* __restrict__ ks,
                            float* __restrict__ di) {
    long long row = blockIdx.x;
    int th = (int)(row >> 9);
    const float* qr = qp + row * NBF;
    const float* k = ks + (long long)th * NBF;
    float s = 0.f;
    for (int f = threadIdx.x; f < NBF; f += 256) s += qr[f] * k[f];
    s = blk_sum(s);
    if (threadIdx.x == 0) di[row] = 1.0f / s;
}

// ---------------- host ----------------
static float* symf(const void* s) { void* p = nullptr; cudaGetSymbolAddress(&p, s); return (float*)p; }
static hf*    symh(const void* s) { void* p = nullptr; cudaGetSymbolAddress(&p, s); return (hf*)p; }

static void conv(const float* src, long long szh, long long szl, int rs, int cs,
                 int R, int C, int RT, int CT, hf* hi, hf* lo, int nb) {
    conv_kernel<<<nb * RT * CT, 256>>>(src, szh, szl, rs, cs, R, C, RT, CT, hi, lo);
}
static void tg(const hf* Ah, const hf* Al, const hf* Bh, const hf* Bl, float* C,
               int Mv, int Nv, int KT, int MT, int NT, int batch,
               long long sAh, long long sAl, long long sBh, long long sBl,
               long long sCh, long long sCl, int ldc, int cstr,
               const float* bias, long long sbh, long long sbl,
               const float* rs, long long srh, long long srl, float alpha, int relu) {
    dim3 grid(NT, MT, batch);
    tgemm<<<grid, 256, SMEM_DYN>>>(Ah, Al, Bh, Bl, C, Mv, Nv, KT, sAh, sAl, sBh, sBl,
                                   sCh, sCl, ldc, cstr, bias, sbh, sbl, rs, srh, srl, alpha, relu);
}

extern "C" void kernel_launch(void* const* d_in, const int* in_sizes, int n_in,
                              void* d_out, int out_size) {
    (void)in_sizes; (void)n_in; (void)out_size;
    const float* x_ctx = (const float*)d_in[0];
    const float* label = (const float*)d_in[1];
    const float* x_tgt = (const float*)d_in[2];
    const float* W1 = (const float*)d_in[3];  const float* b1 = (const float*)d_in[4];
    const float* W2 = (const float*)d_in[5];  const float* b2 = (const float*)d_in[6];
    const float* W3 = (const float*)d_in[7];  const float* b3 = (const float*)d_in[8];
    const float* Wk = (const float*)d_in[9];  const float* bk = (const float*)d_in[10];
    const float* Wv = (const float*)d_in[11]; const float* bv = (const float*)d_in[12];
    const float* Wq = (const float*)d_in[13]; const float* bq = (const float*)d_in[14];
    const float* Wo = (const float*)d_in[15]; const float* bo = (const float*)d_in[16];
    const float* Wmu = (const float*)d_in[17]; const float* bmu = (const float*)d_in[18];
    const float* proj = (const float*)d_in[19];
    float* out = (float*)d_out;

    cudaFuncSetAttribute(tgemm, cudaFuncAttributeMaxDynamicSharedMemorySize, SMEM_DYN);

    float *xc = symf(g_xc), *h1 = symf(g_h1), *h2 = symf(g_h2), *cf = symf(g_cf);
    float *kb = symf(g_k), *vb = symf(g_v), *qb = symf(g_q);
    float *qp = symf(g_qp), *kp = symf(g_kp), *ksum = symf(g_ksum);
    float *kmxp = symf(g_kmxp), *dinv = symf(g_dinv), *ctx = symf(g_ctx);
    float *om = symf(g_om), *rep = symf(g_rep);
    hf *Ah = symh(pAh), *Al = symh(pAl), *Bh = symh(pBh), *Bl = symh(pBl);

    // 1) task encoder MLP
    concat_kernel<<<TT * NCC, 256>>>(x_ctx, label, xc);
    conv(xc, 0, 0, 259, 1, 4096, 259, 32, 5, Ah, Al, 1);
    conv(W1, 0, 0, 1, 256, 256, 259, 2, 5, Bh, Bl, 1);
    tg(Ah, Al, Bh, Bl, h1, 4096, 256, 5, 32, 2, 1, 0,0,0,0, 0,0, 256,1, b1,0,0, nullptr,0,0, 1.f, 1);
    conv(h1, 0, 0, 256, 1, 4096, 256, 32, 4, Ah, Al, 1);
    conv(W2, 0, 0, 1, 256, 256, 256, 2, 4, Bh, Bl, 1);
    tg(Ah, Al, Bh, Bl, h2, 4096, 256, 4, 32, 2, 1, 0,0,0,0, 0,0, 256,1, b2,0,0, nullptr,0,0, 1.f, 1);
    conv(h2, 0, 0, 256, 1, 4096, 256, 32, 4, Ah, Al, 1);
    conv(W3, 0, 0, 1, 256, 256, 256, 2, 4, Bh, Bl, 1);
    tg(Ah, Al, Bh, Bl, cf, 4096, 256, 4, 32, 2, 1, 0,0,0,0, 0,0, 256,1, b3,0,0, nullptr,0,0, 1.f, 1);

    // 2) per-head k/v/q projections -> [t,h,n,e]; z = t*8+h
    conv(x_ctx, 0, 0, 256, 1, 4096, 256, 32, 4, Ah, Al, 1);
    conv(Wk, 0, 65536, 1, 256, 256, 256, 2, 4, Bh, Bl, 8);
    tg(Ah, Al, Bh, Bl, kb, 512, 256, 4, 4, 2, 64, 131072,0, 0,65536,
       1048576,131072, 256,1, bk,0,256, nullptr,0,0, 1.f, 0);
    conv(cf, 0, 0, 256, 1, 4096, 256, 32, 4, Ah, Al, 1);
    conv(Wv, 0, 65536, 1, 256, 256, 256, 2, 4, Bh, Bl, 8);
    tg(Ah, Al, Bh, Bl, vb, 512, 256, 4, 4, 2, 64, 131072,0, 0,65536,
       1048576,131072, 256,1, bv,0,256, nullptr,0,0, 1.f, 0);
    conv(x_tgt, 0, 0, 256, 1, 4096, 256, 32, 4, Ah, Al, 1);
    conv(Wq, 0, 65536, 1, 256, 256, 256, 2, 4, Bh, Bl, 8);
    tg(Ah, Al, Bh, Bl, qb, 512, 256, 4, 4, 2, 64, 131072,0, 0,65536,
       1048576,131072, 256,1, bq,0,256, nullptr,0,0, 1.f, 0);

    // 3) FAVOR+ projections: dd = DN * X @ proj^T
    conv(proj, 0, 0, 256, 1, 1419, 256, 12, 4, Bh, Bl, 1);
    conv(qb, 0, 0, 256, 1, 32768, 256, 256, 4, Ah, Al, 1);
    tg(Ah, Al, Bh, Bl, qp, 32768, NBF, 4, 256, 12, 1, 0,0,0,0, 0,0, NBF,1,
       nullptr,0,0, nullptr,0,0, DN, 0);
    conv(kb, 0, 0, 256, 1, 32768, 256, 256, 4, Ah, Al, 1);
    tg(Ah, Al, Bh, Bl, kp, 32768, NBF, 4, 256, 12, 1, 0,0,0,0, 0,0, NBF,1,
       nullptr,0,0, nullptr,0,0, DN, 0);

    // 4) softmax-kernel transforms
    kmax_kernel<<<dim3(8, TT * HH), 256>>>(kp, kmxp);
    kfeat_kernel<<<TT * HH * NCC, 256>>>(kp, kb, kmxp);
    qfeat_kernel<<<TT * HH * NTT, 256>>>(qp, qb);
    ksum_kernel<<<dim3(12, TT * HH), 128>>>(kp, ksum);
    dinv_kernel<<<TT * HH * NTT, 256>>>(qp, ksum, dinv);

    // 5) ctx[z] = kp[z]^T @ v[z]
    conv(kp, 8LL*726528, 726528, 1, 1419, 1419, 512, 12, 8, Ah, Al, 64);
    conv(vb, 8LL*131072, 131072, 1, 256, 256, 512, 2, 8, Bh, Bl, 64);
    tg(Ah, Al, Bh, Bl, ctx, NBF, 256, 8, 12, 2, 64, 8LL*786432,786432, 8LL*131072,131072,
       8LL*363264,363264, 256,1, nullptr,0,0, nullptr,0,0, 1.f, 0);

    // 6) om = (qp @ ctx) * dinv, head-interleaved store
    conv(qp, 8LL*726528, 726528, 1419, 1, 512, 1419, 4, 23, Ah, Al, 64);
    conv(ctx, 8LL*363264, 363264, 1, 256, 256, 1419, 2, 23, Bh, Bl, 64);
    tg(Ah, Al, Bh, Bl, om, 512, 256, 23, 4, 2, 64, 8LL*753664,753664, 8LL*376832,376832,
       1048576,1, 2048,8, nullptr,0,0, dinv,4096,512, 1.f, 0);

    // 7) rep = om @ Wo + bo ; out = rep @ Wmu + bmu
    conv(om, 0, 0, 2048, 1, 4096, 2048, 32, 32, Ah, Al, 1);
    conv(Wo, 0, 0, 1, 256, 256, 2048, 2, 32, Bh, Bl, 1);
    tg(Ah, Al, Bh, Bl, rep, 4096, 256, 32, 32, 2, 1, 0,0,0,0, 0,0, 256,1,
       bo,0,0, nullptr,0,0, 1.f, 0);
    conv(rep, 0, 0, 256, 1, 4096, 256, 32, 4, Ah, Al, 1);
    conv(Wmu, 0, 0, 1, 256, 256, 256, 2, 4, Bh, Bl, 1);
    tg(Ah, Al, Bh, Bl, out, 4096, 256, 4, 32, 2, 1, 0,0,0,0, 0,0, 256,1,
       bmu,0,0, nullptr,0,0, 1.f, 0);
}

// round 17
// speedup vs baseline: 2.5354x; 1.0672x over previous
#include <cuda_runtime.h>
#include <cuda_fp16.h>
#include <math.h>
#include <stdint.h>

#define TT 8
#define NCC 512
#define NTT 512
#define DD 256
#define HH 8
#define LBL 3
#define NBF 1419
#define EPS_ 1e-4f
#define DN 0.25f
#define DN2 0.0625f
#define RATIO 0.026549364f
#define LSC 2048.0f
#define ILSC (1.0f / 2048.0f)
#define PSC 16384.0f
#define IPSC (1.0f / 16384.0f)

typedef __half hf;

// ---------------- fp32 scratch ----------------
__device__ float g_xc[TT*NCC*(DD+LBL)];
__device__ float g_h1[TT*NCC*DD];
__device__ float g_h2[TT*NCC*DD];
__device__ float g_cf[TT*NCC*DD];
__device__ float g_k[TT*HH*NCC*DD];
__device__ float g_v[TT*HH*NCC*DD];
__device__ float g_q[TT*HH*NTT*DD];
__device__ float g_qp[(long long)TT*HH*NTT*NBF];
__device__ float g_kp[(long long)TT*HH*NCC*NBF];
__device__ float g_ksum[TT*HH*NBF];
__device__ float g_kmxp[TT*HH*8];
__device__ float g_dinv[TT*HH*NTT];
__device__ float g_ctx[(long long)TT*HH*NBF*DD];
__device__ float g_om[TT*NTT*HH*DD];
__device__ float g_rep[TT*NTT*DD];

// ---------------- fp16 operand pools ----------------
#define PA_SZ 50331648LL
#define PB_SZ 24117248LL
__device__ __align__(16) hf pAh[PA_SZ], pAl[PA_SZ];
__device__ __align__(16) hf pBh[PB_SZ], pBl[PB_SZ];

// ---------------- PTX helpers ----------------
__device__ __forceinline__ uint32_t smem_u32(const void* p) {
    uint32_t a;
    asm("{ .reg .u64 t; cvta.to.shared.u64 t, %1; cvt.u32.u64 %0, t; }" : "=r"(a) : "l"(p));
    return a;
}
__device__ __forceinline__ void cpa16(uint32_t s, const void* g) {
    asm volatile("cp.async.cg.shared.global [%0], [%1], 16;" :: "r"(s), "l"(g));
}
__device__ __forceinline__ void ldsm4(uint32_t* r, uint32_t addr) {
    asm volatile("ldmatrix.sync.aligned.m8n8.x4.shared.b16 {%0,%1,%2,%3}, [%4];"
        : "=r"(r[0]), "=r"(r[1]), "=r"(r[2]), "=r"(r[3]) : "r"(addr));
}
__device__ __forceinline__ void mmaF(float* c, const uint32_t* a, uint32_t b0, uint32_t b1) {
    asm volatile("mma.sync.aligned.m16n8k16.row.col.f32.f16.f16.f32 "
        "{%0,%1,%2,%3}, {%4,%5,%6,%7}, {%8,%9}, {%0,%1,%2,%3};"
        : "+f"(c[0]), "+f"(c[1]), "+f"(c[2]), "+f"(c[3])
        : "r"(a[0]), "r"(a[1]), "r"(a[2]), "r"(a[3]), "r"(b0), "r"(b1));
}
__device__ __forceinline__ uint32_t swz(uint32_t off) {
    return off ^ ((off >> 3) & 0x70);
}

// ======= fp32 -> (hi, lo*2^11) fp16, pre-scaled by psc, tiled 128x64, SW128 =======
__global__ __launch_bounds__(256) void conv_kernel(
    const float* __restrict__ src, long long szh, long long szl,
    int rs_, int cs_, int R, int C, int RT, int CT,
    hf* __restrict__ hi, hf* __restrict__ lo, int wlo, float psc)
{
    __shared__ float sh[128][65];
    int tile = blockIdx.x;
    int ct = tile % CT, rt = (tile / CT) % RT, z = tile / (CT * RT);
    const float* s = src + (long long)(z >> 3) * szh + (long long)(z & 7) * szl;
    int r0 = rt * 128, c0 = ct * 64, tid = threadIdx.x;
    if (rs_ == 1) {
#pragma unroll 4
        for (int it = 0; it < 32; ++it) {
            int e = it * 256 + tid, r = e & 127, c = e >> 7;
            int gr = r0 + r, gc = c0 + c;
            sh[r][c] = (gr < R && gc < C) ? s[(long long)gr + (long long)gc * cs_] : 0.f;
        }
    } else {
#pragma unroll 4
        for (int it = 0; it < 32; ++it) {
            int e = it * 256 + tid, r = e >> 6, c = e & 63;
            int gr = r0 + r, gc = c0 + c;
            sh[r][c] = (gr < R && gc < C) ? s[(long long)gr * rs_ + (long long)gc * cs_] : 0.f;
        }
    }
    __syncthreads();
    long long tb = (long long)tile * 8192;
#pragma unroll
    for (int it = 0; it < 4; ++it) {
        int p0 = (it * 256 + tid) * 8;
        uint32_t lb = swz((uint32_t)(p0 * 2));
        int q0 = lb >> 1, r = q0 >> 6, c = q0 & 63;
        hf hv[8], lv[8];
#pragma unroll
        for (int j = 0; j < 8; ++j) {
            float x = sh[r][c + j] * psc;
            hf h = __float2half(x);
            hv[j] = h;
            lv[j] = __float2half((x - __half2float(h)) * LSC);
        }
        *(uint4*)(hi + tb + p0) = *(const uint4*)hv;
        if (wlo) *(uint4*)(lo + tb + p0) = *(const uint4*)lv;
    }
}

// ======= split-fp16 GEMM: D = alpha*A@B^T (+bias)(relu)(*rowScale) =======
// NM3=1: main + A_hi*B_lo + A_lo*B_hi (corrections f32 accC, lo scaled 2^11)
// NM3=0: main + A_hi*B_lo only (A_lo never loaded; A pre-scaled to normal range)
#define SMEM_DYN (2 * 65536)

template<int NM3>
__global__ __launch_bounds__(256, 1)
void tgemm(const hf* __restrict__ Ahi, const hf* __restrict__ Alo,
           const hf* __restrict__ Bhi, const hf* __restrict__ Blo,
           float* __restrict__ C, int Mv, int Nv, int KT,
           long long sAh, long long sAl, long long sBh, long long sBl,
           long long sCh, long long sCl, int ldc, int cstride,
           const float* __restrict__ bias, long long sbh, long long sbl,
           const float* __restrict__ rsc, long long srh, long long srl,
           float alpha, int relu)
{
    extern __shared__ __align__(16) char dsm[];
    uint32_t base = smem_u32(dsm);

    int tid = threadIdx.x, wid = tid >> 5, lane = tid & 31;
    int z = blockIdx.z, mt = blockIdx.y, nt = blockIdx.x;
    int zh = z >> 3, zl = z & 7;

    const char* Ah = (const char*)(Ahi + zh * sAh + zl * sAl + (long long)mt * KT * 8192);
    const char* Al = (const char*)(Alo + zh * sAh + zl * sAl + (long long)mt * KT * 8192);
    const char* Bh = (const char*)(Bhi + zh * sBh + zl * sBl + (long long)nt * KT * 8192);
    const char* Bl = (const char*)(Blo + zh * sBh + zl * sBl + (long long)nt * KT * 8192);

    int warp_m = wid >> 2, warp_n = wid & 3;
    uint32_t aOff = (uint32_t)(warp_m * 64 + (lane & 15)) * 128 + ((lane >> 4) << 4);
    uint32_t bOff = (uint32_t)(warp_n * 32 + (lane & 7) + ((lane >> 4) << 3)) * 128
                  + (((lane >> 3) & 1) << 4);

    float accF[4][4][4], accC[4][4][4];
#pragma unroll
    for (int i = 0; i < 4; i++)
#pragma unroll
        for (int j = 0; j < 4; j++)
#pragma unroll
            for (int l = 0; l < 4; l++) { accF[i][j][l] = 0.f; accC[i][j][l] = 0.f; }

    // prologue: stage 0 <- chunk 0
    {
        uint32_t so = base;
#pragma unroll
        for (int i = 0; i < 4; ++i) {
            uint32_t off = tid * 16 + i * 4096;
            cpa16(so + off,         Ah + off);
            if (NM3) cpa16(so + 16384 + off, Al + off);
            cpa16(so + 32768 + off, Bh + off);
            cpa16(so + 49152 + off, Bl + off);
        }
        asm volatile("cp.async.commit_group;" ::: "memory");
    }

    for (int kt = 0; kt < KT; ++kt) {
        int s = kt & 1;
        if (kt + 1 < KT) {
            uint32_t so = base + (s ^ 1) * 65536;
            long long kb = (long long)(kt + 1) * 16384;
#pragma unroll
            for (int i = 0; i < 4; ++i) {
                uint32_t off = tid * 16 + i * 4096;
                cpa16(so + off,         Ah + kb + off);
                if (NM3) cpa16(so + 16384 + off, Al + kb + off);
                cpa16(so + 32768 + off, Bh + kb + off);
                cpa16(so + 49152 + off, Bl + kb + off);
            }
            asm volatile("cp.async.commit_group;" ::: "memory");
            asm volatile("cp.async.wait_group 1;" ::: "memory");
        } else {
            asm volatile("cp.async.wait_group 0;" ::: "memory");
        }
        __syncthreads();

        uint32_t sb = base + s * 65536;
#pragma unroll
        for (int ks = 0; ks < 4; ++ks) {
            uint32_t kb = ks * 32;
            uint32_t b_h[2][4], b_l[2][4];
#pragma unroll
            for (int p = 0; p < 2; ++p) {
                uint32_t o = swz(bOff + p * 2048 + kb);
                ldsm4(b_h[p], sb + 32768 + o);
                ldsm4(b_l[p], sb + 49152 + o);
            }
#pragma unroll
            for (int m = 0; m < 4; ++m) {
                uint32_t o = swz(aOff + m * 2048 + kb);
                uint32_t a_h[4];
                ldsm4(a_h, sb + o);
#pragma unroll
                for (int p = 0; p < 2; ++p)
#pragma unroll
                    for (int sub = 0; sub < 2; ++sub) {
                        int n = p * 2 + sub;
                        mmaF(accF[m][n], a_h, b_h[p][sub*2], b_h[p][sub*2+1]);
                        mmaF(accC[m][n], a_h, b_l[p][sub*2], b_l[p][sub*2+1]);
                    }
                if (NM3) {
                    uint32_t a_l[4];
                    ldsm4(a_l, sb + 16384 + o);
#pragma unroll
                    for (int p = 0; p < 2; ++p)
#pragma unroll
                        for (int sub = 0; sub < 2; ++sub) {
                            int n = p * 2 + sub;
                            mmaF(accC[m][n], a_l, b_h[p][sub*2], b_h[p][sub*2+1]);
                        }
                }
            }
        }
        __syncthreads();
    }

    // ---- epilogue: main + corrections * 2^-11 ----
    float* Cp = C + (long long)zh * sCh + (long long)zl * sCl;
    const float* bp = bias ? bias + zh * sbh + zl * sbl : nullptr;
    const float* rp = rsc  ? rsc  + zh * srh + zl * srl : nullptr;
    int g = lane >> 2, t4 = lane & 3;
#pragma unroll
    for (int m = 0; m < 4; ++m) {
        int r0 = mt * 128 + warp_m * 64 + m * 16 + g;
        float rv0 = (rp && r0     < Mv) ? rp[r0]     : 1.f;
        float rv1 = (rp && r0 + 8 < Mv) ? rp[r0 + 8] : 1.f;
#pragma unroll
        for (int n = 0; n < 4; ++n) {
            int c0 = nt * 128 + warp_n * 32 + n * 8 + t4 * 2;
#pragma unroll
            for (int e = 0; e < 2; ++e) {
                int col = c0 + e;
                if (col >= Nv) continue;
                float badd = bp ? bp[col] : 0.f;
                if (r0 < Mv) {
                    float v = (accF[m][n][e] + accC[m][n][e] * ILSC) * alpha + badd;
                    if (relu) v = fmaxf(v, 0.f);
                    Cp[(long long)r0 * ldc + (long long)col * cstride] = v * rv0;
                }
                if (r0 + 8 < Mv) {
                    float v = (accF[m][n][2 + e] + accC[m][n][2 + e] * ILSC) * alpha + badd;
                    if (relu) v = fmaxf(v, 0.f);
                    Cp[(long long)(r0 + 8) * ldc + (long long)col * cstride] = v * rv1;
                }
            }
        }
    }
}

// ---------------- reductions ----------------
__device__ __forceinline__ float blk_sum(float v) {
    __shared__ float sh[32];
    int lane = threadIdx.x & 31, w = threadIdx.x >> 5;
#pragma unroll
    for (int o = 16; o; o >>= 1) v += __shfl_xor_sync(0xffffffffu, v, o);
    __syncthreads();
    if (lane == 0) sh[w] = v;
    __syncthreads();
    float r = (threadIdx.x < (blockDim.x >> 5)) ? sh[threadIdx.x] : 0.f;
    if (w == 0) {
#pragma unroll
        for (int o = 16; o; o >>= 1) r += __shfl_xor_sync(0xffffffffu, r, o);
        if (lane == 0) sh[0] = r;
    }
    __syncthreads();
    return sh[0];
}
__device__ __forceinline__ float blk_max(float v) {
    __shared__ float sh[32];
    int lane = threadIdx.x & 31, w = threadIdx.x >> 5;
#pragma unroll
    for (int o = 16; o; o >>= 1) v = fmaxf(v, __shfl_xor_sync(0xffffffffu, v, o));
    __syncthreads();
    if (lane == 0) sh[w] = v;
    __syncthreads();
    float r = (threadIdx.x < (blockDim.x >> 5)) ? sh[threadIdx.x] : -INFINITY;
    if (w == 0) {
#pragma unroll
        for (int o = 16; o; o >>= 1) r = fmaxf(r, __shfl_xor_sync(0xffffffffu, r, o));
        if (lane == 0) sh[0] = r;
    }
    __syncthreads();
    return sh[0];
}

// ---------------- elementwise ----------------
__global__ void concat_kernel(const float* __restrict__ x, const float* __restrict__ l,
                              float* __restrict__ o) {
    int r = blockIdx.x, t = threadIdx.x;
    o[(long long)r * 259 + t] = x[(long long)r * 256 + t];
    if (t < LBL) o[(long long)r * 259 + 256 + t] = l[(long long)r * LBL + t];
}
__global__ void qfeat_kernel(float* __restrict__ dd, const float* __restrict__ q) {
    long long row = blockIdx.x;
    const float* qr = q + row * DD;
    float* d = dd + row * NBF;
    int t = threadIdx.x;
    float qv = qr[t];
    float diag = 0.5f * blk_sum(qv * qv) * DN2;
    float mx = -INFINITY;
    for (int f = t; f < NBF; f += 256) mx = fmaxf(mx, d[f]);
    mx = blk_max(mx);
    float sub = diag + mx;
    for (int f = t; f < NBF; f += 256) d[f] = RATIO * (__expf(d[f] - sub) + EPS_);
}
__global__ void kmax_kernel(const float* __restrict__ dd, float* __restrict__ km) {
    int th = blockIdx.y, ch = blockIdx.x;
    const float* b = dd + ((long long)th * NCC + (long long)ch * 64) * NBF;
    float mx = -INFINITY;
    for (long long i = threadIdx.x; i < (long long)64 * NBF; i += blockDim.x)
        mx = fmaxf(mx, b[i]);
    mx = blk_max(mx);
    if (threadIdx.x == 0) km[th * 8 + ch] = mx;
}
__global__ void kfeat_kernel(float* __restrict__ dd, const float* __restrict__ k,
                             const float* __restrict__ km) {
    long long row = blockIdx.x;
    int th = (int)(row >> 9), t = threadIdx.x;
    const float* kr = k + row * DD;
    float* d = dd + row * NBF;
    float kv = kr[t];
    float diag = 0.5f * blk_sum(kv * kv) * DN2;
    float mx = -INFINITY;
#pragma unroll
    for (int c = 0; c < 8; c++) mx = fmaxf(mx, km[th * 8 + c]);
    float sub = diag + mx;
    for (int f = t; f < NBF; f += 256) d[f] = RATIO * (__expf(d[f] - sub) + EPS_);
}
__global__ void ksum_kernel(const float* __restrict__ kp, float* __restrict__ ks) {
    int th = blockIdx.y, f = blockIdx.x * 128 + threadIdx.x;
    if (f >= NBF) return;
    const float* b = kp + (long long)th * NCC * NBF + f;
    float s = 0.f;
    for (int n = 0; n < NCC; n++) s += b[(long long)n * NBF];
    ks[(long long)th * NBF + f] = s;
}
__global__ void dinv_kernel(const float* __restrict__ qp, const float* __restrict__ ks,
                            float* __restrict__ di) {
    long long row = blockIdx.x;
    int th = (int)(row >> 9);
    const float* qr = qp + row * NBF;
    const float* k = ks + (long long)th * NBF;
    float s = 0.f;
    for (int f = threadIdx.x; f < NBF; f += 256) s += qr[f] * k[f];
    s = blk_sum(s);
    if (threadIdx.x == 0) di[row] = 1.0f / s;
}

// ---------------- host ----------------
static float* symf(const void* s) { void* p = nullptr; cudaGetSymbolAddress(&p, s); return (float*)p; }
static hf*    symh(const void* s) { void* p = nullptr; cudaGetSymbolAddress(&p, s); return (hf*)p; }

static void conv(const float* src, long long szh, long long szl, int rs, int cs,
                 int R, int C, int RT, int CT, hf* hi, hf* lo, int nb,
                 int wlo = 1, float psc = 1.f) {
    conv_kernel<<<nb * RT * CT, 256>>>(src, szh, szl, rs, cs, R, C, RT, CT, hi, lo, wlo, psc);
}
static void tg(const hf* Ah, const hf* Al, const hf* Bh, const hf* Bl, float* C,
               int Mv, int Nv, int KT, int MT, int NT, int batch,
               long long sAh, long long sAl, long long sBh, long long sBl,
               long long sCh, long long sCl, int ldc, int cstr,
               const float* bias, long long sbh, long long sbl,
               const float* rs, long long srh, long long srl, float alpha, int relu,
               int nm3 = 1) {
    dim3 grid(NT, MT, batch);
    if (nm3)
        tgemm<1><<<grid, 256, SMEM_DYN>>>(Ah, Al, Bh, Bl, C, Mv, Nv, KT, sAh, sAl, sBh, sBl,
                                          sCh, sCl, ldc, cstr, bias, sbh, sbl, rs, srh, srl,
                                          alpha, relu);
    else
        tgemm<0><<<grid, 256, SMEM_DYN>>>(Ah, Al, Bh, Bl, C, Mv, Nv, KT, sAh, sAl, sBh, sBl,
                                          sCh, sCl, ldc, cstr, bias, sbh, sbl, rs, srh, srl,
                                          alpha, relu);
}

extern "C" void kernel_launch(void* const* d_in, const int* in_sizes, int n_in,
                              void* d_out, int out_size) {
    (void)in_sizes; (void)n_in; (void)out_size;
    const float* x_ctx = (const float*)d_in[0];
    const float* label = (const float*)d_in[1];
    const float* x_tgt = (const float*)d_in[2];
    const float* W1 = (const float*)d_in[3];  const float* b1 = (const float*)d_in[4];
    const float* W2 = (const float*)d_in[5];  const float* b2 = (const float*)d_in[6];
    const float* W3 = (const float*)d_in[7];  const float* b3 = (const float*)d_in[8];
    const float* Wk = (const float*)d_in[9];  const float* bk = (const float*)d_in[10];
    const float* Wv = (const float*)d_in[11]; const float* bv = (const float*)d_in[12];
    const float* Wq = (const float*)d_in[13]; const float* bq = (const float*)d_in[14];
    const float* Wo = (const float*)d_in[15]; const float* bo = (const float*)d_in[16];
    const float* Wmu = (const float*)d_in[17]; const float* bmu = (const float*)d_in[18];
    const float* proj = (const float*)d_in[19];
    float* out = (float*)d_out;

    cudaFuncSetAttribute(tgemm<1>, cudaFuncAttributeMaxDynamicSharedMemorySize, SMEM_DYN);
    cudaFuncSetAttribute(tgemm<0>, cudaFuncAttributeMaxDynamicSharedMemorySize, SMEM_DYN);

    float *xc = symf(g_xc), *h1 = symf(g_h1), *h2 = symf(g_h2), *cf = symf(g_cf);
    float *kb = symf(g_k), *vb = symf(g_v), *qb = symf(g_q);
    float *qp = symf(g_qp), *kp = symf(g_kp), *ksum = symf(g_ksum);
    float *kmxp = symf(g_kmxp), *dinv = symf(g_dinv), *ctx = symf(g_ctx);
    float *om = symf(g_om), *rep = symf(g_rep);
    hf *Ah = symh(pAh), *Al = symh(pAl), *Bh = symh(pBh), *Bl = symh(pBl);

    // 1) task encoder MLP (3-MMA)
    concat_kernel<<<TT * NCC, 256>>>(x_ctx, label, xc);
    conv(xc, 0, 0, 259, 1, 4096, 259, 32, 5, Ah, Al, 1);
    conv(W1, 0, 0, 1, 256, 256, 259, 2, 5, Bh, Bl, 1);
    tg(Ah, Al, Bh, Bl, h1, 4096, 256, 5, 32, 2, 1, 0,0,0,0, 0,0, 256,1, b1,0,0, nullptr,0,0, 1.f, 1);
    conv(h1, 0, 0, 256, 1, 4096, 256, 32, 4, Ah, Al, 1);
    conv(W2, 0, 0, 1, 256, 256, 256, 2, 4, Bh, Bl, 1);
    tg(Ah, Al, Bh, Bl, h2, 4096, 256, 4, 32, 2, 1, 0,0,0,0, 0,0, 256,1, b2,0,0, nullptr,0,0, 1.f, 1);
    conv(h2, 0, 0, 256, 1, 4096, 256, 32, 4, Ah, Al, 1);
    conv(W3, 0, 0, 1, 256, 256, 256, 2, 4, Bh, Bl, 1);
    tg(Ah, Al, Bh, Bl, cf, 4096, 256, 4, 32, 2, 1, 0,0,0,0, 0,0, 256,1, b3,0,0, nullptr,0,0, 1.f, 1);

    // 2) per-head k/v/q projections -> [t,h,n,e]; z = t*8+h (3-MMA)
    conv(x_ctx, 0, 0, 256, 1, 4096, 256, 32, 4, Ah, Al, 1);
    conv(Wk, 0, 65536, 1, 256, 256, 256, 2, 4, Bh, Bl, 8);
    tg(Ah, Al, Bh, Bl, kb, 512, 256, 4, 4, 2, 64, 131072,0, 0,65536,
       1048576,131072, 256,1, bk,0,256, nullptr,0,0, 1.f, 0);
    conv(cf, 0, 0, 256, 1, 4096, 256, 32, 4, Ah, Al, 1);
    conv(Wv, 0, 65536, 1, 256, 256, 256, 2, 4, Bh, Bl, 8);
    tg(Ah, Al, Bh, Bl, vb, 512, 256, 4, 4, 2, 64, 131072,0, 0,65536,
       1048576,131072, 256,1, bv,0,256, nullptr,0,0, 1.f, 0);
    conv(x_tgt, 0, 0, 256, 1, 4096, 256, 32, 4, Ah, Al, 1);
    conv(Wq, 0, 65536, 1, 256, 256, 256, 2, 4, Bh, Bl, 8);
    tg(Ah, Al, Bh, Bl, qb, 512, 256, 4, 4, 2, 64, 131072,0, 0,65536,
       1048576,131072, 256,1, bq,0,256, nullptr,0,0, 1.f, 0);

    // 3) FAVOR+ projections: dd = DN * X @ proj^T (3-MMA: feeds exp)
    conv(proj, 0, 0, 256, 1, 1419, 256, 12, 4, Bh, Bl, 1);
    conv(qb, 0, 0, 256, 1, 32768, 256, 256, 4, Ah, Al, 1);
    tg(Ah, Al, Bh, Bl, qp, 32768, NBF, 4, 256, 12, 1, 0,0,0,0, 0,0, NBF,1,
       nullptr,0,0, nullptr,0,0, DN, 0);
    conv(kb, 0, 0, 256, 1, 32768, 256, 256, 4, Ah, Al, 1);
    tg(Ah, Al, Bh, Bl, kp, 32768, NBF, 4, 256, 12, 1, 0,0,0,0, 0,0, NBF,1,
       nullptr,0,0, nullptr,0,0, DN, 0);

    // 4) softmax-kernel transforms
    kmax_kernel<<<dim3(8, TT * HH), 256>>>(kp, kmxp);
    kfeat_kernel<<<TT * HH * NCC, 256>>>(kp, kb, kmxp);
    qfeat_kernel<<<TT * HH * NTT, 256>>>(qp, qb);
    ksum_kernel<<<dim3(12, TT * HH), 128>>>(kp, ksum);
    dinv_kernel<<<TT * HH * NTT, 256>>>(qp, ksum, dinv);

    // 5) ctx[z] = kp[z]^T @ v[z]  (2-MMA; A = kp * 2^14 so all entries fp16-normal)
    conv(kp, 8LL*726528, 726528, 1, 1419, 1419, 512, 12, 8, Ah, Al, 64, 0, PSC);
    conv(vb, 8LL*131072, 131072, 1, 256, 256, 512, 2, 8, Bh, Bl, 64);
    tg(Ah, Al, Bh, Bl, ctx, NBF, 256, 8, 12, 2, 64, 8LL*786432,786432, 8LL*131072,131072,
       8LL*363264,363264, 256,1, nullptr,0,0, nullptr,0,0, IPSC, 0, 0);

    // 6) om = (qp @ ctx) * dinv  (2-MMA; A = qp * 2^14)
    conv(qp, 8LL*726528, 726528, 1419, 1, 512, 1419, 4, 23, Ah, Al, 64, 0, PSC);
    conv(ctx, 8LL*363264, 363264, 1, 256, 256, 1419, 2, 23, Bh, Bl, 64);
    tg(Ah, Al, Bh, Bl, om, 512, 256, 23, 4, 2, 64, 8LL*753664,753664, 8LL*376832,376832,
       1048576,1, 2048,8, nullptr,0,0, dinv,4096,512, IPSC, 0, 0);

    // 7) rep = om @ Wo + bo ; out = rep @ Wmu + bmu (3-MMA)
    conv(om, 0, 0, 2048, 1, 4096, 2048, 32, 32, Ah, Al, 1);
    conv(Wo, 0, 0, 1, 256, 256, 2048, 2, 32, Bh, Bl, 1);
    tg(Ah, Al, Bh, Bl, rep, 4096, 256, 32, 32, 2, 1, 0,0,0,0, 0,0, 256,1,
       bo,0,0, nullptr,0,0, 1.f, 0);
    conv(rep, 0, 0, 256, 1, 4096, 256, 32, 4, Ah, Al, 1);
    conv(Wmu, 0, 0, 1, 256, 256, 256, 2, 4, Bh, Bl, 1);
    tg(Ah, Al, Bh, Bl, out, 4096, 256, 4, 32, 2, 1, 0,0,0,0, 0,0, 256,1,
       bmu,0,0, nullptr,0,0, 1.f, 0);
}